// round 2
// baseline (speedup 1.0000x reference)
#include <cuda_runtime.h>
#include <math.h>

// ---------------------------------------------------------------------------
// MultidomainEncoder: B=4, N=M=1024, H=512.
// fp32 baseline: tiled SGEMM + two-pass softmax + fused add-layernorm.
// All scratch in __device__ globals (no allocation inside kernel_launch).
// ---------------------------------------------------------------------------

#define RR   4096          // B*N == B*M rows
#define HD   512           // model dim

__device__ float g_e [RR * HD];
__device__ float g_e1[RR * HD];
__device__ float g_e2[RR * HD];
__device__ float g_e3[RR * HD];
__device__ float g_K [RR * HD];
__device__ float g_V [RR * HD];
__device__ float g_Q [RR * HD];
__device__ float g_K2[RR * HD];
__device__ float g_V2[RR * HD];
__device__ float g_Q2[RR * HD];
__device__ float g_R [RR * HD];
__device__ float g_T [RR * HD];
__device__ float g_qb[RR * HD];
__device__ float g_kb[RR * HD];
__device__ float g_S [(size_t)16 * 1024 * 1024];   // up to B*h*N*N (h=4) fp32 = 64 MB

// ---------------------------------------------------------------------------
// Generic batched SGEMM:  C = alpha * A @ op(B) [+ bias] [+ C]
// A: M x K (row-major, lda), B: K x N (transB=0) or N x K (transB=1)
// Batched over grid.z = nb*nh; per-z pointer offsets b*s?b + h*s?h.
// All of M, N divisible by 64 and K divisible by 16 in this problem.
// ---------------------------------------------------------------------------
#define BM 64
#define BN 64
#define BK 16

__global__ void gemm_kernel(const float* __restrict__ A, const float* __restrict__ B,
                            float* __restrict__ C, const float* __restrict__ bias,
                            int M, int N, int K, int lda, int ldb, int ldc,
                            long sAb, long sAh, long sBb, long sBh, long sCb, long sCh,
                            int nh, float alpha, int transB, int accumulate)
{
    __shared__ float As[BK][BM];
    __shared__ float Bs[BK][BN + 1];

    int z  = blockIdx.z;
    int bb = z / nh;
    int hh = z - bb * nh;
    A += (long)bb * sAb + (long)hh * sAh;
    B += (long)bb * sBb + (long)hh * sBh;
    C += (long)bb * sCb + (long)hh * sCh;

    int row0 = blockIdx.y * BM;
    int col0 = blockIdx.x * BN;
    int tx = threadIdx.x, ty = threadIdx.y;
    int tid = ty * 16 + tx;

    float acc[4][4] = {};

    for (int k0 = 0; k0 < K; k0 += BK) {
        // Load A tile (BM x BK) transposed into As[k][m]
#pragma unroll
        for (int i = 0; i < 4; i++) {
            int idx = tid + i * 256;
            int m = idx >> 4;
            int k = idx & 15;
            As[k][m] = A[(long)(row0 + m) * lda + k0 + k];
        }
        if (!transB) {
#pragma unroll
            for (int i = 0; i < 4; i++) {
                int idx = tid + i * 256;
                int n = idx & 63;
                int k = idx >> 6;
                Bs[k][n] = B[(long)(k0 + k) * ldb + col0 + n];
            }
        } else {
#pragma unroll
            for (int i = 0; i < 4; i++) {
                int idx = tid + i * 256;
                int k = idx & 15;
                int n = idx >> 4;
                Bs[k][n] = B[(long)(col0 + n) * ldb + k0 + k];
            }
        }
        __syncthreads();

#pragma unroll
        for (int k = 0; k < BK; k++) {
            float a[4], bv[4];
#pragma unroll
            for (int i = 0; i < 4; i++) a[i] = As[k][ty * 4 + i];
#pragma unroll
            for (int j = 0; j < 4; j++) bv[j] = Bs[k][tx * 4 + j];
#pragma unroll
            for (int i = 0; i < 4; i++)
#pragma unroll
                for (int j = 0; j < 4; j++)
                    acc[i][j] += a[i] * bv[j];
        }
        __syncthreads();
    }

#pragma unroll
    for (int i = 0; i < 4; i++) {
        int r = row0 + ty * 4 + i;
#pragma unroll
        for (int j = 0; j < 4; j++) {
            int c = col0 + tx * 4 + j;
            float v = alpha * acc[i][j];
            if (bias)       v += bias[c];
            if (accumulate) v += C[(long)r * ldc + c];
            C[(long)r * ldc + c] = v;
        }
    }
}

// ---------------------------------------------------------------------------
// Row softmax, in place. One block (256 thr) per row of length L.
// ---------------------------------------------------------------------------
__global__ void softmax_kernel(float* __restrict__ S, int L)
{
    long row = blockIdx.x;
    float* p = S + row * (long)L;
    __shared__ float red[256];
    int tid = threadIdx.x;

    float m = -1e30f;
    for (int i = tid; i < L; i += 256) m = fmaxf(m, p[i]);
    red[tid] = m; __syncthreads();
    for (int s = 128; s > 0; s >>= 1) { if (tid < s) red[tid] = fmaxf(red[tid], red[tid + s]); __syncthreads(); }
    m = red[0]; __syncthreads();

    float sum = 0.f;
    for (int i = tid; i < L; i += 256) { float ev = __expf(p[i] - m); p[i] = ev; sum += ev; }
    red[tid] = sum; __syncthreads();
    for (int s = 128; s > 0; s >>= 1) { if (tid < s) red[tid] += red[tid + s]; __syncthreads(); }
    float inv = 1.f / red[0];
    for (int i = tid; i < L; i += 256) p[i] *= inv;
}

// ---------------------------------------------------------------------------
// out = LayerNorm(tmp + res) * g + b     (row length 512, 256 threads/row)
// Safe in-place with out == res.
// ---------------------------------------------------------------------------
__global__ void add_ln_kernel(const float* __restrict__ tmp, const float* __restrict__ res,
                              const float* __restrict__ g, const float* __restrict__ b,
                              float* __restrict__ out)
{
    long row = blockIdx.x;
    const float* t = tmp + row * (long)HD;
    const float* r = res + row * (long)HD;
    float* o = out + row * (long)HD;
    __shared__ float red[256];
    int tid = threadIdx.x;

    float v0 = t[tid]       + r[tid];
    float v1 = t[tid + 256] + r[tid + 256];
    red[tid] = v0 + v1; __syncthreads();
    for (int s = 128; s > 0; s >>= 1) { if (tid < s) red[tid] += red[tid + s]; __syncthreads(); }
    float mean = red[0] * (1.f / HD);
    __syncthreads();
    float d0 = v0 - mean, d1 = v1 - mean;
    red[tid] = d0 * d0 + d1 * d1; __syncthreads();
    for (int s = 128; s > 0; s >>= 1) { if (tid < s) red[tid] += red[tid + s]; __syncthreads(); }
    float rstd = rsqrtf(red[0] * (1.f / HD) + 1e-5f);
    o[tid]       = d0 * rstd * g[tid]       + b[tid];
    o[tid + 256] = d1 * rstd * g[tid + 256] + b[tid + 256];
}

// ---------------------------------------------------------------------------
// Input projections
// ---------------------------------------------------------------------------
// e = concat([context_x, context_y[:, :, j, :]], -1) @ in_W(3xH) + in_b
__global__ void proj_in_kernel(const float* __restrict__ cx, const float* __restrict__ cy,
                               const float* __restrict__ W, const float* __restrict__ bias,
                               float* __restrict__ out, int j)
{
    int idx = blockIdx.x * blockDim.x + threadIdx.x;
    if (idx >= RR * HD) return;
    int r = idx >> 9;
    int h = idx & (HD - 1);
    float x0 = cx[r];
    float y0 = cy[r * 8 + j * 2];
    float y1 = cy[r * 8 + j * 2 + 1];
    out[idx] = x0 * W[h] + y0 * W[HD + h] + y1 * W[2 * HD + h] + bias[h];
}

// out = x(R,1) @ W(1,H) + b
__global__ void proj1_kernel(const float* __restrict__ x, const float* __restrict__ W,
                             const float* __restrict__ bias, float* __restrict__ out)
{
    int idx = blockIdx.x * blockDim.x + threadIdx.x;
    if (idx >= RR * HD) return;
    int r = idx >> 9;
    int h = idx & (HD - 1);
    out[idx] = x[r] * W[h] + bias[h];
}

// ---------------------------------------------------------------------------
// Host-side orchestration
// ---------------------------------------------------------------------------
static inline void gemm(const float* A, const float* B, float* C, const float* bias,
                        int M, int N, int K, int lda, int ldb, int ldc,
                        long sAb, long sAh, long sBb, long sBh, long sCb, long sCh,
                        int nb, int nh, float alpha, int transB, int acc)
{
    dim3 grid(N / BN, M / BM, nb * nh);
    dim3 block(16, 16);
    gemm_kernel<<<grid, block>>>(A, B, C, bias, M, N, K, lda, ldb, ldc,
                                 sAb, sAh, sBb, sBh, sCb, sCh, nh, alpha, transB, acc);
}

struct Bufs {
    float *e, *e1, *e2, *e3, *K, *V, *Q, *K2, *V2, *Q2, *R, *T, *qb, *kb, *S;
};

// One self/cross encoder layer: x <- LN(x + concat([x, r]) @ Wf + bf)
static void sc_attn(Bufs& Z, float* x, float* x2,
                    const float* Wk, const float* Wv, const float* Wq,
                    const float* Wf, const float* bf, const float* gg, const float* bb)
{
    const int hn = 2, d = 256, Nn = 1024, Bb = 4;
    const float scale = rsqrtf((float)d);

    gemm(x, Wk, Z.K, nullptr, RR, HD, HD, HD, HD, HD, 0,0,0,0,0,0, 1,1, 1.f, 0, 0);
    gemm(x, Wv, Z.V, nullptr, RR, HD, HD, HD, HD, HD, 0,0,0,0,0,0, 1,1, 1.f, 0, 0);
    gemm(x, Wq, Z.Q, nullptr, RR, HD, HD, HD, HD, HD, 0,0,0,0,0,0, 1,1, 1.f, 0, 0);

    bool same = (x2 == x);
    if (!same) {
        gemm(x2, Wk, Z.K2, nullptr, RR, HD, HD, HD, HD, HD, 0,0,0,0,0,0, 1,1, 1.f, 0, 0);
        gemm(x2, Wv, Z.V2, nullptr, RR, HD, HD, HD, HD, HD, 0,0,0,0,0,0, 1,1, 1.f, 0, 0);
        gemm(x2, Wq, Z.Q2, nullptr, RR, HD, HD, HD, HD, HD, 0,0,0,0,0,0, 1,1, 1.f, 0, 0);
    }

    // sdpa(sQ,sK,sV)+sdpa(cQ,cK,cV)+sdpa(cQ,sK,sV)+sdpa(sQ,cK,cV); all equal when x2==x.
    const float* Qs[4] = { Z.Q, Z.Q2, Z.Q2, Z.Q };
    const float* Ks[4] = { Z.K, Z.K2, Z.K,  Z.K2 };
    const float* Vs[4] = { Z.V, Z.V2, Z.V,  Z.V2 };
    int   ncomb   = same ? 1 : 4;
    float avalpha = same ? 4.f : 1.f;

    for (int c = 0; c < ncomb; c++) {
        // S[b,h] = (Q_slice @ K_slice^T) * scale
        gemm(Qs[c], Ks[c], Z.S, nullptr,
             Nn, Nn, d, HD, HD, Nn,
             (long)Nn * HD, d, (long)Nn * HD, d, (long)hn * Nn * Nn, (long)Nn * Nn,
             Bb, hn, scale, 1, 0);
        softmax_kernel<<<Bb * hn * Nn, 256>>>(Z.S, Nn);
        // r_slice (+)= alpha * S @ V_slice
        gemm(Z.S, Vs[c], Z.R, nullptr,
             Nn, d, Nn, Nn, HD, HD,
             (long)hn * Nn * Nn, (long)Nn * Nn, (long)Nn * HD, d, (long)Nn * HD, d,
             Bb, hn, avalpha, 0, c > 0 ? 1 : 0);
    }

    // tmp = x @ Wf[0:H] + r @ Wf[H:2H] + bf   (concat-free)
    gemm(x,   Wf,           Z.T, bf,      RR, HD, HD, HD, HD, HD, 0,0,0,0,0,0, 1,1, 1.f, 0, 0);
    gemm(Z.R, Wf + HD * HD, Z.T, nullptr, RR, HD, HD, HD, HD, HD, 0,0,0,0,0,0, 1,1, 1.f, 0, 1);

    add_ln_kernel<<<RR, 256>>>(Z.T, x, gg, bb, x);
}

// One decoder cross-attn layer (h=4): q <- LN(q + concat([q, sdpa]) @ Wf + bf)
static void cross_attn(Bufs& Z, float* qv, float* kv, float* ev,
                       const float* Wk, const float* Wv, const float* Wq,
                       const float* Wf, const float* bf, const float* gg, const float* bb)
{
    const int hn = 4, d = 128, Nn = 1024, Bb = 4;
    const float scale = rsqrtf((float)d);

    gemm(kv, Wk, Z.K, nullptr, RR, HD, HD, HD, HD, HD, 0,0,0,0,0,0, 1,1, 1.f, 0, 0);
    gemm(ev, Wv, Z.V, nullptr, RR, HD, HD, HD, HD, HD, 0,0,0,0,0,0, 1,1, 1.f, 0, 0);
    gemm(qv, Wq, Z.Q, nullptr, RR, HD, HD, HD, HD, HD, 0,0,0,0,0,0, 1,1, 1.f, 0, 0);

    gemm(Z.Q, Z.K, Z.S, nullptr,
         Nn, Nn, d, HD, HD, Nn,
         (long)Nn * HD, d, (long)Nn * HD, d, (long)hn * Nn * Nn, (long)Nn * Nn,
         Bb, hn, scale, 1, 0);
    softmax_kernel<<<Bb * hn * Nn, 256>>>(Z.S, Nn);
    gemm(Z.S, Z.V, Z.R, nullptr,
         Nn, d, Nn, Nn, HD, HD,
         (long)hn * Nn * Nn, (long)Nn * Nn, (long)Nn * HD, d, (long)Nn * HD, d,
         Bb, hn, 1.f, 0, 0);

    gemm(qv,  Wf,           Z.T, bf,      RR, HD, HD, HD, HD, HD, 0,0,0,0,0,0, 1,1, 1.f, 0, 0);
    gemm(Z.R, Wf + HD * HD, Z.T, nullptr, RR, HD, HD, HD, HD, HD, 0,0,0,0,0,0, 1,1, 1.f, 0, 1);

    add_ln_kernel<<<RR, 256>>>(Z.T, qv, gg, bb, qv);
}

extern "C" void kernel_launch(void* const* d_in, const int* in_sizes, int n_in,
                              void* d_out, int out_size)
{
    const float* context_x = (const float*)d_in[0];
    const float* context_y = (const float*)d_in[1];
    const float* target_x  = (const float*)d_in[2];
    const float* in_W = (const float*)d_in[3];
    const float* in_b = (const float*)d_in[4];
    const float* cx_W = (const float*)d_in[5];
    const float* cx_b = (const float*)d_in[6];
    const float* tx_W = (const float*)d_in[7];
    const float* tx_b = (const float*)d_in[8];
    const float* sc_Wk = (const float*)d_in[9];
    const float* sc_Wv = (const float*)d_in[10];
    const float* sc_Wq = (const float*)d_in[11];
    const float* sc_Wf = (const float*)d_in[12];
    const float* sc_bf = (const float*)d_in[13];
    const float* sc_g  = (const float*)d_in[14];
    const float* sc_b  = (const float*)d_in[15];
    const float* ca_Wk = (const float*)d_in[16];
    const float* ca_Wv = (const float*)d_in[17];
    const float* ca_Wq = (const float*)d_in[18];
    const float* ca_Wf = (const float*)d_in[19];
    const float* ca_bf = (const float*)d_in[20];
    const float* ca_g  = (const float*)d_in[21];
    const float* ca_b  = (const float*)d_in[22];

    Bufs Z;
    cudaGetSymbolAddress((void**)&Z.e,  g_e);
    cudaGetSymbolAddress((void**)&Z.e1, g_e1);
    cudaGetSymbolAddress((void**)&Z.e2, g_e2);
    cudaGetSymbolAddress((void**)&Z.e3, g_e3);
    cudaGetSymbolAddress((void**)&Z.K,  g_K);
    cudaGetSymbolAddress((void**)&Z.V,  g_V);
    cudaGetSymbolAddress((void**)&Z.Q,  g_Q);
    cudaGetSymbolAddress((void**)&Z.K2, g_K2);
    cudaGetSymbolAddress((void**)&Z.V2, g_V2);
    cudaGetSymbolAddress((void**)&Z.Q2, g_Q2);
    cudaGetSymbolAddress((void**)&Z.R,  g_R);
    cudaGetSymbolAddress((void**)&Z.T,  g_T);
    cudaGetSymbolAddress((void**)&Z.qb, g_qb);
    cudaGetSymbolAddress((void**)&Z.kb, g_kb);
    cudaGetSymbolAddress((void**)&Z.S,  g_S);

    const int nthr = 256, nblk = (RR * HD + nthr - 1) / nthr;

    // Input projections: e and the three y-slices e1..e3
    proj_in_kernel<<<nblk, nthr>>>(context_x, context_y, in_W, in_b, Z.e,  0);
    proj_in_kernel<<<nblk, nthr>>>(context_x, context_y, in_W, in_b, Z.e1, 1);
    proj_in_kernel<<<nblk, nthr>>>(context_x, context_y, in_W, in_b, Z.e2, 2);
    proj_in_kernel<<<nblk, nthr>>>(context_x, context_y, in_W, in_b, Z.e3, 3);

    const long WW = (long)HD * HD;       // per-layer weight stride for (2,H,H)
    const long WF = 2L * HD * HD;        // per-layer weight stride for (2,2H,H)

    // 2 self layers (x2 == x → single SDPA scaled by 4)
    for (int i = 0; i < 2; i++)
        sc_attn(Z, Z.e, Z.e,
                sc_Wk + i * WW, sc_Wv + i * WW, sc_Wq + i * WW,
                sc_Wf + i * WF, sc_bf + i * HD, sc_g + i * HD, sc_b + i * HD);

    // 3 cross-domain groups x 2 layers
    float* xs2[3] = { Z.e1, Z.e2, Z.e3 };
    for (int s = 0; s < 3; s++)
        for (int i = 0; i < 2; i++)
            sc_attn(Z, Z.e, xs2[s],
                    sc_Wk + i * WW, sc_Wv + i * WW, sc_Wq + i * WW,
                    sc_Wf + i * WF, sc_bf + i * HD, sc_g + i * HD, sc_b + i * HD);

    // Decoder inputs
    proj1_kernel<<<nblk, nthr>>>(target_x,  tx_W, tx_b, Z.qb);
    proj1_kernel<<<nblk, nthr>>>(context_x, cx_W, cx_b, Z.kb);

    // 2 cross-attention layers
    for (int i = 0; i < 2; i++)
        cross_attn(Z, Z.qb, Z.kb, Z.e,
                   ca_Wk + i * WW, ca_Wv + i * WW, ca_Wq + i * WW,
                   ca_Wf + i * WF, ca_bf + i * HD, ca_g + i * HD, ca_b + i * HD);

    cudaMemcpyAsync(d_out, Z.qb, (size_t)RR * HD * sizeof(float),
                    cudaMemcpyDeviceToDevice);
}

// round 4
// speedup vs baseline: 3.5464x; 3.5464x over previous
#include <cuda_runtime.h>
#include <math.h>
#include <stdint.h>

// ---------------------------------------------------------------------------
// MultidomainEncoder: B=4, N=M=1024, H=512.
// Round 2: all GEMMs on tensor cores via TF32 mma.sync.m16n8k8.
// ---------------------------------------------------------------------------

#define RR   4096          // B*N == B*M rows
#define HD   512           // model dim

__device__ float g_e [RR * HD];
__device__ float g_e1[RR * HD];
__device__ float g_e2[RR * HD];
__device__ float g_e3[RR * HD];
__device__ float g_K [RR * HD];
__device__ float g_V [RR * HD];
__device__ float g_Q [RR * HD];
__device__ float g_K2[RR * HD];
__device__ float g_V2[RR * HD];
__device__ float g_Q2[RR * HD];
__device__ float g_R [RR * HD];
__device__ float g_T [RR * HD];
__device__ float g_qb[RR * HD];
__device__ float g_kb[RR * HD];
__device__ float g_S [(size_t)16 * 1024 * 1024];   // up to B*h*N*N fp32

// ---------------------------------------------------------------------------
// TF32 helpers
// ---------------------------------------------------------------------------
__device__ __forceinline__ uint32_t f2tf32(float x) {
    uint32_t r;
    asm("cvt.rna.tf32.f32 %0, %1;" : "=r"(r) : "f"(x));
    return r;
}

__device__ __forceinline__ void mma_tf32(float c[4], const uint32_t a[4], const uint32_t b[2]) {
    asm volatile(
        "mma.sync.aligned.m16n8k8.row.col.f32.tf32.tf32.f32 "
        "{%0,%1,%2,%3}, {%4,%5,%6,%7}, {%8,%9}, {%0,%1,%2,%3};"
        : "+f"(c[0]), "+f"(c[1]), "+f"(c[2]), "+f"(c[3])
        : "r"(a[0]), "r"(a[1]), "r"(a[2]), "r"(a[3]), "r"(b[0]), "r"(b[1]));
}

// ---------------------------------------------------------------------------
// Batched TF32 tensor-core GEMM: C = alpha * A @ op(B) [+ bias] [+ C]
// A: M x K (row-major, lda); B: K x N (transB=0) or N x K (transB=1).
// M, N multiples of 128; K multiple of 16.
// Block: 256 threads (8 warps, 4x2), tile 128x128x16, double-buffered smem.
// ---------------------------------------------------------------------------
#define TBM 128
#define TBN 128
#define TBK 16
#define SPAD 4

__global__ __launch_bounds__(256)
void gemm_tc(const float* __restrict__ A, const float* __restrict__ B,
             float* __restrict__ C, const float* __restrict__ bias,
             int M, int N, int K, int lda, int ldb, int ldc,
             long sAb, long sAh, long sBb, long sBh, long sCb, long sCh,
             int nh, float alpha, int transB, int accumulate)
{
    __shared__ uint32_t As[2][TBK][TBM + SPAD];
    __shared__ uint32_t Bs[2][TBK][TBN + SPAD];

    int z  = blockIdx.z;
    int bb = z / nh;
    int hh = z - bb * nh;
    A += (long)bb * sAb + (long)hh * sAh;
    B += (long)bb * sBb + (long)hh * sBh;
    C += (long)bb * sCb + (long)hh * sCh;

    const int row0 = blockIdx.y * TBM;
    const int col0 = blockIdx.x * TBN;
    const int tid  = threadIdx.x;
    const int warp = tid >> 5;
    const int lane = tid & 31;
    const int wm = warp & 3;            // 4 warps along M
    const int wn = warp >> 2;           // 2 warps along N
    const int warpM0 = wm * 32;
    const int warpN0 = wn * 64;
    const int gid = lane >> 2;          // 0..7
    const int tig = lane & 3;           // 0..3

    float acc[2][8][4];
#pragma unroll
    for (int i = 0; i < 2; i++)
#pragma unroll
        for (int j = 0; j < 8; j++)
#pragma unroll
            for (int v = 0; v < 4; v++) acc[i][j][v] = 0.f;

    // gmem staging indices
    const int ar = tid >> 2;            // 0..63 (A rows; +64 for second half)
    const int ac = (tid & 3) * 4;       // A k-cols (float4)
    const int bk = tid >> 4;            // 0..15 (transB=0: B k-row)
    const int bn = (tid & 15) * 8;      // transB=0: B n-col (2 x float4)

    float rA[8], rB[8];
    const int nK = K / TBK;

    // ---- load tile 0 ----
    {
        const float* Ap = A + (long)(row0 + ar) * lda + ac;
        float4 v0 = *(const float4*)Ap;
        float4 v1 = *(const float4*)(Ap + (long)64 * lda);
        rA[0]=v0.x; rA[1]=v0.y; rA[2]=v0.z; rA[3]=v0.w;
        rA[4]=v1.x; rA[5]=v1.y; rA[6]=v1.z; rA[7]=v1.w;
        if (transB) {
            const float* Bp = B + (long)(col0 + ar) * ldb + ac;
            float4 w0 = *(const float4*)Bp;
            float4 w1 = *(const float4*)(Bp + (long)64 * ldb);
            rB[0]=w0.x; rB[1]=w0.y; rB[2]=w0.z; rB[3]=w0.w;
            rB[4]=w1.x; rB[5]=w1.y; rB[6]=w1.z; rB[7]=w1.w;
        } else {
            const float* Bp = B + (long)bk * ldb + col0 + bn;
            float4 w0 = *(const float4*)Bp;
            float4 w1 = *(const float4*)(Bp + 4);
            rB[0]=w0.x; rB[1]=w0.y; rB[2]=w0.z; rB[3]=w0.w;
            rB[4]=w1.x; rB[5]=w1.y; rB[6]=w1.z; rB[7]=w1.w;
        }
    }
    // store tile 0 to smem buf 0
#pragma unroll
    for (int j = 0; j < 4; j++) {
        As[0][ac + j][ar]      = f2tf32(rA[j]);
        As[0][ac + j][ar + 64] = f2tf32(rA[4 + j]);
    }
    if (transB) {
#pragma unroll
        for (int j = 0; j < 4; j++) {
            Bs[0][ac + j][ar]      = f2tf32(rB[j]);
            Bs[0][ac + j][ar + 64] = f2tf32(rB[4 + j]);
        }
    } else {
#pragma unroll
        for (int j = 0; j < 8; j++) Bs[0][bk][bn + j] = f2tf32(rB[j]);
    }
    __syncthreads();

    int buf = 0;
    for (int t = 0; t < nK; t++) {
        // prefetch next tile into regs
        if (t + 1 < nK) {
            int k0 = (t + 1) * TBK;
            const float* Ap = A + (long)(row0 + ar) * lda + k0 + ac;
            float4 v0 = *(const float4*)Ap;
            float4 v1 = *(const float4*)(Ap + (long)64 * lda);
            rA[0]=v0.x; rA[1]=v0.y; rA[2]=v0.z; rA[3]=v0.w;
            rA[4]=v1.x; rA[5]=v1.y; rA[6]=v1.z; rA[7]=v1.w;
            if (transB) {
                const float* Bp = B + (long)(col0 + ar) * ldb + k0 + ac;
                float4 w0 = *(const float4*)Bp;
                float4 w1 = *(const float4*)(Bp + (long)64 * ldb);
                rB[0]=w0.x; rB[1]=w0.y; rB[2]=w0.z; rB[3]=w0.w;
                rB[4]=w1.x; rB[5]=w1.y; rB[6]=w1.z; rB[7]=w1.w;
            } else {
                const float* Bp = B + (long)(k0 + bk) * ldb + col0 + bn;
                float4 w0 = *(const float4*)Bp;
                float4 w1 = *(const float4*)(Bp + 4);
                rB[0]=w0.x; rB[1]=w0.y; rB[2]=w0.z; rB[3]=w0.w;
                rB[4]=w1.x; rB[5]=w1.y; rB[6]=w1.z; rB[7]=w1.w;
            }
        }

        // compute on buf
#pragma unroll
        for (int kk = 0; kk < TBK; kk += 8) {
            uint32_t af[2][4], bf[8][2];
#pragma unroll
            for (int mt = 0; mt < 2; mt++) {
                int m = warpM0 + mt * 16 + gid;
                af[mt][0] = As[buf][kk + tig][m];
                af[mt][1] = As[buf][kk + tig][m + 8];
                af[mt][2] = As[buf][kk + tig + 4][m];
                af[mt][3] = As[buf][kk + tig + 4][m + 8];
            }
#pragma unroll
            for (int nt = 0; nt < 8; nt++) {
                int n = warpN0 + nt * 8 + gid;
                bf[nt][0] = Bs[buf][kk + tig][n];
                bf[nt][1] = Bs[buf][kk + tig + 4][n];
            }
#pragma unroll
            for (int nt = 0; nt < 8; nt++)
#pragma unroll
                for (int mt = 0; mt < 2; mt++)
                    mma_tf32(acc[mt][nt], af[mt], bf[nt]);
        }

        // store prefetched tile to other buffer
        if (t + 1 < nK) {
            int nb = buf ^ 1;
#pragma unroll
            for (int j = 0; j < 4; j++) {
                As[nb][ac + j][ar]      = f2tf32(rA[j]);
                As[nb][ac + j][ar + 64] = f2tf32(rA[4 + j]);
            }
            if (transB) {
#pragma unroll
                for (int j = 0; j < 4; j++) {
                    Bs[nb][ac + j][ar]      = f2tf32(rB[j]);
                    Bs[nb][ac + j][ar + 64] = f2tf32(rB[4 + j]);
                }
            } else {
#pragma unroll
                for (int j = 0; j < 8; j++) Bs[nb][bk][bn + j] = f2tf32(rB[j]);
            }
            __syncthreads();
        }
        buf ^= 1;
    }

    // ---- epilogue ----
#pragma unroll
    for (int mt = 0; mt < 2; mt++) {
        int r0 = row0 + warpM0 + mt * 16 + gid;
#pragma unroll
        for (int nt = 0; nt < 8; nt++) {
            int c0 = col0 + warpN0 + nt * 8 + tig * 2;
#pragma unroll
            for (int v = 0; v < 4; v++) {
                int r = r0 + (v >> 1) * 8;
                int c = c0 + (v & 1);
                float val = alpha * acc[mt][nt][v];
                if (bias)       val += bias[c];
                if (accumulate) val += C[(long)r * ldc + c];
                C[(long)r * ldc + c] = val;
            }
        }
    }
}

// ---------------------------------------------------------------------------
// Row softmax, in place. One block (256 thr) per row of length L.
// ---------------------------------------------------------------------------
__global__ void softmax_kernel(float* __restrict__ S, int L)
{
    long row = blockIdx.x;
    float* p = S + row * (long)L;
    __shared__ float red[256];
    int tid = threadIdx.x;

    float m = -1e30f;
    for (int i = tid; i < L; i += 256) m = fmaxf(m, p[i]);
    red[tid] = m; __syncthreads();
    for (int s = 128; s > 0; s >>= 1) { if (tid < s) red[tid] = fmaxf(red[tid], red[tid + s]); __syncthreads(); }
    m = red[0]; __syncthreads();

    float sum = 0.f;
    for (int i = tid; i < L; i += 256) { float ev = __expf(p[i] - m); p[i] = ev; sum += ev; }
    red[tid] = sum; __syncthreads();
    for (int s = 128; s > 0; s >>= 1) { if (tid < s) red[tid] += red[tid + s]; __syncthreads(); }
    float inv = 1.f / red[0];
    for (int i = tid; i < L; i += 256) p[i] *= inv;
}

// ---------------------------------------------------------------------------
// out = LayerNorm(tmp + res) * g + b     (row length 512, 256 threads/row)
// ---------------------------------------------------------------------------
__global__ void add_ln_kernel(const float* __restrict__ tmp, const float* __restrict__ res,
                              const float* __restrict__ g, const float* __restrict__ b,
                              float* __restrict__ out)
{
    long row = blockIdx.x;
    const float* t = tmp + row * (long)HD;
    const float* r = res + row * (long)HD;
    float* o = out + row * (long)HD;
    __shared__ float red[256];
    int tid = threadIdx.x;

    float v0 = t[tid]       + r[tid];
    float v1 = t[tid + 256] + r[tid + 256];
    red[tid] = v0 + v1; __syncthreads();
    for (int s = 128; s > 0; s >>= 1) { if (tid < s) red[tid] += red[tid + s]; __syncthreads(); }
    float mean = red[0] * (1.f / HD);
    __syncthreads();
    float d0 = v0 - mean, d1 = v1 - mean;
    red[tid] = d0 * d0 + d1 * d1; __syncthreads();
    for (int s = 128; s > 0; s >>= 1) { if (tid < s) red[tid] += red[tid + s]; __syncthreads(); }
    float rstd = rsqrtf(red[0] * (1.f / HD) + 1e-5f);
    o[tid]       = d0 * rstd * g[tid]       + b[tid];
    o[tid + 256] = d1 * rstd * g[tid + 256] + b[tid + 256];
}

// ---------------------------------------------------------------------------
// Input projections
// ---------------------------------------------------------------------------
__global__ void proj_in_kernel(const float* __restrict__ cx, const float* __restrict__ cy,
                               const float* __restrict__ W, const float* __restrict__ bias,
                               float* __restrict__ out, int j)
{
    int idx = blockIdx.x * blockDim.x + threadIdx.x;
    if (idx >= RR * HD) return;
    int r = idx >> 9;
    int h = idx & (HD - 1);
    float x0 = cx[r];
    float y0 = cy[r * 8 + j * 2];
    float y1 = cy[r * 8 + j * 2 + 1];
    out[idx] = x0 * W[h] + y0 * W[HD + h] + y1 * W[2 * HD + h] + bias[h];
}

__global__ void proj1_kernel(const float* __restrict__ x, const float* __restrict__ W,
                             const float* __restrict__ bias, float* __restrict__ out)
{
    int idx = blockIdx.x * blockDim.x + threadIdx.x;
    if (idx >= RR * HD) return;
    int r = idx >> 9;
    int h = idx & (HD - 1);
    out[idx] = x[r] * W[h] + bias[h];
}

// ---------------------------------------------------------------------------
// Host-side orchestration
// ---------------------------------------------------------------------------
static inline void gemm(const float* A, const float* B, float* C, const float* bias,
                        int M, int N, int K, int lda, int ldb, int ldc,
                        long sAb, long sAh, long sBb, long sBh, long sCb, long sCh,
                        int nb, int nh, float alpha, int transB, int acc)
{
    dim3 grid(N / TBN, M / TBM, nb * nh);
    gemm_tc<<<grid, 256>>>(A, B, C, bias, M, N, K, lda, ldb, ldc,
                           sAb, sAh, sBb, sBh, sCb, sCh, nh, alpha, transB, acc);
}

struct Bufs {
    float *e, *e1, *e2, *e3, *K, *V, *Q, *K2, *V2, *Q2, *R, *T, *qb, *kb, *S;
};

static void sc_attn(Bufs& Z, float* x, float* x2,
                    const float* Wk, const float* Wv, const float* Wq,
                    const float* Wf, const float* bf, const float* gg, const float* bb)
{
    const int hn = 2, d = 256, Nn = 1024, Bb = 4;
    const float scale = rsqrtf((float)d);

    gemm(x, Wk, Z.K, nullptr, RR, HD, HD, HD, HD, HD, 0,0,0,0,0,0, 1,1, 1.f, 0, 0);
    gemm(x, Wv, Z.V, nullptr, RR, HD, HD, HD, HD, HD, 0,0,0,0,0,0, 1,1, 1.f, 0, 0);
    gemm(x, Wq, Z.Q, nullptr, RR, HD, HD, HD, HD, HD, 0,0,0,0,0,0, 1,1, 1.f, 0, 0);

    bool same = (x2 == x);
    if (!same) {
        gemm(x2, Wk, Z.K2, nullptr, RR, HD, HD, HD, HD, HD, 0,0,0,0,0,0, 1,1, 1.f, 0, 0);
        gemm(x2, Wv, Z.V2, nullptr, RR, HD, HD, HD, HD, HD, 0,0,0,0,0,0, 1,1, 1.f, 0, 0);
        gemm(x2, Wq, Z.Q2, nullptr, RR, HD, HD, HD, HD, HD, 0,0,0,0,0,0, 1,1, 1.f, 0, 0);
    }

    const float* Qs[4] = { Z.Q, Z.Q2, Z.Q2, Z.Q };
    const float* Ks[4] = { Z.K, Z.K2, Z.K,  Z.K2 };
    const float* Vs[4] = { Z.V, Z.V2, Z.V,  Z.V2 };
    int   ncomb   = same ? 1 : 4;
    float avalpha = same ? 4.f : 1.f;

    for (int c = 0; c < ncomb; c++) {
        gemm(Qs[c], Ks[c], Z.S, nullptr,
             Nn, Nn, d, HD, HD, Nn,
             (long)Nn * HD, d, (long)Nn * HD, d, (long)hn * Nn * Nn, (long)Nn * Nn,
             Bb, hn, scale, 1, 0);
        softmax_kernel<<<Bb * hn * Nn, 256>>>(Z.S, Nn);
        gemm(Z.S, Vs[c], Z.R, nullptr,
             Nn, d, Nn, Nn, HD, HD,
             (long)hn * Nn * Nn, (long)Nn * Nn, (long)Nn * HD, d, (long)Nn * HD, d,
             Bb, hn, avalpha, 0, c > 0 ? 1 : 0);
    }

    gemm(x,   Wf,           Z.T, bf,      RR, HD, HD, HD, HD, HD, 0,0,0,0,0,0, 1,1, 1.f, 0, 0);
    gemm(Z.R, Wf + HD * HD, Z.T, nullptr, RR, HD, HD, HD, HD, HD, 0,0,0,0,0,0, 1,1, 1.f, 0, 1);

    add_ln_kernel<<<RR, 256>>>(Z.T, x, gg, bb, x);
}

static void cross_attn(Bufs& Z, float* qv, float* kv, float* ev,
                       const float* Wk, const float* Wv, const float* Wq,
                       const float* Wf, const float* bf, const float* gg, const float* bb)
{
    const int hn = 4, d = 128, Nn = 1024, Bb = 4;
    const float scale = rsqrtf((float)d);

    gemm(kv, Wk, Z.K, nullptr, RR, HD, HD, HD, HD, HD, 0,0,0,0,0,0, 1,1, 1.f, 0, 0);
    gemm(ev, Wv, Z.V, nullptr, RR, HD, HD, HD, HD, HD, 0,0,0,0,0,0, 1,1, 1.f, 0, 0);
    gemm(qv, Wq, Z.Q, nullptr, RR, HD, HD, HD, HD, HD, 0,0,0,0,0,0, 1,1, 1.f, 0, 0);

    gemm(Z.Q, Z.K, Z.S, nullptr,
         Nn, Nn, d, HD, HD, Nn,
         (long)Nn * HD, d, (long)Nn * HD, d, (long)hn * Nn * Nn, (long)Nn * Nn,
         Bb, hn, scale, 1, 0);
    softmax_kernel<<<Bb * hn * Nn, 256>>>(Z.S, Nn);
    gemm(Z.S, Z.V, Z.R, nullptr,
         Nn, d, Nn, Nn, HD, HD,
         (long)hn * Nn * Nn, (long)Nn * Nn, (long)Nn * HD, d, (long)Nn * HD, d,
         Bb, hn, 1.f, 0, 0);

    gemm(qv,  Wf,           Z.T, bf,      RR, HD, HD, HD, HD, HD, 0,0,0,0,0,0, 1,1, 1.f, 0, 0);
    gemm(Z.R, Wf + HD * HD, Z.T, nullptr, RR, HD, HD, HD, HD, HD, 0,0,0,0,0,0, 1,1, 1.f, 0, 1);

    add_ln_kernel<<<RR, 256>>>(Z.T, qv, gg, bb, qv);
}

extern "C" void kernel_launch(void* const* d_in, const int* in_sizes, int n_in,
                              void* d_out, int out_size)
{
    const float* context_x = (const float*)d_in[0];
    const float* context_y = (const float*)d_in[1];
    const float* target_x  = (const float*)d_in[2];
    const float* in_W = (const float*)d_in[3];
    const float* in_b = (const float*)d_in[4];
    const float* cx_W = (const float*)d_in[5];
    const float* cx_b = (const float*)d_in[6];
    const float* tx_W = (const float*)d_in[7];
    const float* tx_b = (const float*)d_in[8];
    const float* sc_Wk = (const float*)d_in[9];
    const float* sc_Wv = (const float*)d_in[10];
    const float* sc_Wq = (const float*)d_in[11];
    const float* sc_Wf = (const float*)d_in[12];
    const float* sc_bf = (const float*)d_in[13];
    const float* sc_g  = (const float*)d_in[14];
    const float* sc_b  = (const float*)d_in[15];
    const float* ca_Wk = (const float*)d_in[16];
    const float* ca_Wv = (const float*)d_in[17];
    const float* ca_Wq = (const float*)d_in[18];
    const float* ca_Wf = (const float*)d_in[19];
    const float* ca_bf = (const float*)d_in[20];
    const float* ca_g  = (const float*)d_in[21];
    const float* ca_b  = (const float*)d_in[22];

    Bufs Z;
    cudaGetSymbolAddress((void**)&Z.e,  g_e);
    cudaGetSymbolAddress((void**)&Z.e1, g_e1);
    cudaGetSymbolAddress((void**)&Z.e2, g_e2);
    cudaGetSymbolAddress((void**)&Z.e3, g_e3);
    cudaGetSymbolAddress((void**)&Z.K,  g_K);
    cudaGetSymbolAddress((void**)&Z.V,  g_V);
    cudaGetSymbolAddress((void**)&Z.Q,  g_Q);
    cudaGetSymbolAddress((void**)&Z.K2, g_K2);
    cudaGetSymbolAddress((void**)&Z.V2, g_V2);
    cudaGetSymbolAddress((void**)&Z.Q2, g_Q2);
    cudaGetSymbolAddress((void**)&Z.R,  g_R);
    cudaGetSymbolAddress((void**)&Z.T,  g_T);
    cudaGetSymbolAddress((void**)&Z.qb, g_qb);
    cudaGetSymbolAddress((void**)&Z.kb, g_kb);
    cudaGetSymbolAddress((void**)&Z.S,  g_S);

    const int nthr = 256, nblk = (RR * HD + nthr - 1) / nthr;

    proj_in_kernel<<<nblk, nthr>>>(context_x, context_y, in_W, in_b, Z.e,  0);
    proj_in_kernel<<<nblk, nthr>>>(context_x, context_y, in_W, in_b, Z.e1, 1);
    proj_in_kernel<<<nblk, nthr>>>(context_x, context_y, in_W, in_b, Z.e2, 2);
    proj_in_kernel<<<nblk, nthr>>>(context_x, context_y, in_W, in_b, Z.e3, 3);

    const long WW = (long)HD * HD;
    const long WF = 2L * HD * HD;

    for (int i = 0; i < 2; i++)
        sc_attn(Z, Z.e, Z.e,
                sc_Wk + i * WW, sc_Wv + i * WW, sc_Wq + i * WW,
                sc_Wf + i * WF, sc_bf + i * HD, sc_g + i * HD, sc_b + i * HD);

    float* xs2[3] = { Z.e1, Z.e2, Z.e3 };
    for (int s = 0; s < 3; s++)
        for (int i = 0; i < 2; i++)
            sc_attn(Z, Z.e, xs2[s],
                    sc_Wk + i * WW, sc_Wv + i * WW, sc_Wq + i * WW,
                    sc_Wf + i * WF, sc_bf + i * HD, sc_g + i * HD, sc_b + i * HD);

    proj1_kernel<<<nblk, nthr>>>(target_x,  tx_W, tx_b, Z.qb);
    proj1_kernel<<<nblk, nthr>>>(context_x, cx_W, cx_b, Z.kb);

    for (int i = 0; i < 2; i++)
        cross_attn(Z, Z.qb, Z.kb, Z.e,
                   ca_Wk + i * WW, ca_Wv + i * WW, ca_Wq + i * WW,
                   ca_Wf + i * WF, ca_bf + i * HD, ca_g + i * HD, ca_b + i * HD);

    cudaMemcpyAsync(d_out, Z.qb, (size_t)RR * HD * sizeof(float),
                    cudaMemcpyDeviceToDevice);
}

// round 5
// speedup vs baseline: 4.1442x; 1.1686x over previous
#include <cuda_runtime.h>
#include <math.h>
#include <stdint.h>

// ---------------------------------------------------------------------------
// MultidomainEncoder: B=4, N=M=1024, H=512.
// Round 4: cp.async double-buffered TF32 GEMM, conflict-free smem, 64x64 warp
// tiles, pre-rounded operands (no cvt in GEMM), fused QKV, 1-pass softmax.
// ---------------------------------------------------------------------------

#define RR   4096          // B*N == B*M rows
#define HD   512           // model dim
#define QW   1536          // fused QKV row width

__device__ float g_e  [RR * HD];
__device__ float g_e1 [RR * HD];
__device__ float g_e2 [RR * HD];
__device__ float g_e3 [RR * HD];
__device__ float g_er [RR * HD];   // tf32-rounded copy of e
__device__ float g_qb [RR * HD];
__device__ float g_qbr[RR * HD];   // tf32-rounded copy of qb
__device__ float g_kbr[RR * HD];   // rounded kb (GEMM operand only)
__device__ float g_R  [RR * HD];
__device__ float g_T  [RR * HD];
__device__ float g_QKV [RR * QW];
__device__ float g_QKV2[RR * QW];
__device__ float g_S  [(size_t)16 * 1024 * 1024];
__device__ float g_Wc [4 * 512 * QW];     // fused+rounded QKV weights: sc0,sc1,ca0,ca1
__device__ float g_Wf [4 * 512 * 1024];   // rounded Wf: sc0,sc1,ca0,ca1

// ---------------------------------------------------------------------------
// TF32 helpers
// ---------------------------------------------------------------------------
__device__ __forceinline__ float tf32r(float x) {
    uint32_t r;
    asm("cvt.rna.tf32.f32 %0, %1;" : "=r"(r) : "f"(x));
    return __uint_as_float(r);
}

__device__ __forceinline__ void mma_tf32(float c[4], const uint32_t a[4], const uint32_t b[2]) {
    asm volatile(
        "mma.sync.aligned.m16n8k8.row.col.f32.tf32.tf32.f32 "
        "{%0,%1,%2,%3}, {%4,%5,%6,%7}, {%8,%9}, {%0,%1,%2,%3};"
        : "+f"(c[0]), "+f"(c[1]), "+f"(c[2]), "+f"(c[3])
        : "r"(a[0]), "r"(a[1]), "r"(a[2]), "r"(a[3]), "r"(b[0]), "r"(b[1]));
}

__device__ __forceinline__ void cp16(float* dst, const float* src) {
    uint32_t d = (uint32_t)__cvta_generic_to_shared(dst);
    asm volatile("cp.async.cg.shared.global [%0], [%1], 16;" :: "r"(d), "l"(src));
}
#define CP_COMMIT() asm volatile("cp.async.commit_group;" ::: "memory")
#define CP_WAIT0()  asm volatile("cp.async.wait_group 0;"  ::: "memory")

// ---------------------------------------------------------------------------
// Batched TF32 GEMM: C = alpha * A @ op(B) [+ bias] [+ C], optional tf32 round.
// Operands MUST already be tf32-rounded fp32 (raw bits fed to MMA).
// Tile 128x128x16, 128 threads (4 warps, 2x2 of 64x64), cp.async 2-stage.
// M, N multiples of 128; K multiple of 16.
// ---------------------------------------------------------------------------
#define TBK 16
#define AP  20     // pitch (floats) for A and trans-B tiles: banks 20*gid+tig -> conflict-free
#define BP  136    // pitch for non-trans B tiles: banks 8*tig+gid -> conflict-free
#define STG 2560   // floats per operand per stage

template<bool TB>
__global__ __launch_bounds__(128)
void gemm_tc(const float* __restrict__ A, const float* __restrict__ B,
             float* __restrict__ C, const float* __restrict__ bias,
             int K, int lda, int ldb, int ldc,
             long sAb, long sAh, long sBb, long sBh, long sCb, long sCh,
             int nh, float alpha, int accumulate, int roundOut)
{
    __shared__ float sA[2][STG];
    __shared__ float sB[2][STG];

    int z  = blockIdx.z;
    int bb = z / nh;
    int hh = z - bb * nh;
    A += (long)bb * sAb + (long)hh * sAh;
    B += (long)bb * sBb + (long)hh * sBh;
    C += (long)bb * sCb + (long)hh * sCh;

    const int row0 = blockIdx.y * 128;
    const int col0 = blockIdx.x * 128;
    const int tid  = threadIdx.x;
    const int warp = tid >> 5;
    const int lane = tid & 31;
    const int wM0 = (warp & 1) * 64;
    const int wN0 = (warp >> 1) * 64;
    const int gid = lane >> 2;
    const int tig = lane & 3;

    float acc[4][8][4] = {};

    auto loadA = [&](int t, int s) {
        const float* g = A + (long)(row0 + tid) * lda + t * TBK;
        float* sp = sA[s] + tid * AP;
        cp16(sp, g); cp16(sp + 4, g + 4); cp16(sp + 8, g + 8); cp16(sp + 12, g + 12);
    };
    auto loadB = [&](int t, int s) {
        if (TB) {
            const float* g = B + (long)(col0 + tid) * ldb + t * TBK;
            float* sp = sB[s] + tid * AP;
            cp16(sp, g); cp16(sp + 4, g + 4); cp16(sp + 8, g + 8); cp16(sp + 12, g + 12);
        } else {
            int kr = tid >> 3, jc = (tid & 7) * 4;
            const float* g = B + (long)(t * TBK + kr) * ldb + col0 + jc;
            float* sp = sB[s] + kr * BP + jc;
            cp16(sp, g); cp16(sp + 32, g + 32); cp16(sp + 64, g + 64); cp16(sp + 96, g + 96);
        }
    };

    const int nK = K / TBK;
    loadA(0, 0); loadB(0, 0);
    CP_COMMIT();

    for (int t = 0; t < nK; t++) {
        CP_WAIT0();
        __syncthreads();
        int s = t & 1;
        if (t + 1 < nK) {
            loadA(t + 1, s ^ 1); loadB(t + 1, s ^ 1);
            CP_COMMIT();
        }
        const float* Ap = sA[s];
        const float* Bp = sB[s];
#pragma unroll
        for (int kk = 0; kk < TBK; kk += 8) {
            uint32_t af[4][4], bf[8][2];
#pragma unroll
            for (int mt = 0; mt < 4; mt++) {
                int m = wM0 + mt * 16 + gid;
                af[mt][0] = __float_as_uint(Ap[m * AP + kk + tig]);
                af[mt][1] = __float_as_uint(Ap[(m + 8) * AP + kk + tig]);
                af[mt][2] = __float_as_uint(Ap[m * AP + kk + tig + 4]);
                af[mt][3] = __float_as_uint(Ap[(m + 8) * AP + kk + tig + 4]);
            }
#pragma unroll
            for (int nt = 0; nt < 8; nt++) {
                int n = wN0 + nt * 8 + gid;
                if (TB) {
                    bf[nt][0] = __float_as_uint(Bp[n * AP + kk + tig]);
                    bf[nt][1] = __float_as_uint(Bp[n * AP + kk + tig + 4]);
                } else {
                    bf[nt][0] = __float_as_uint(Bp[(kk + tig) * BP + n]);
                    bf[nt][1] = __float_as_uint(Bp[(kk + tig + 4) * BP + n]);
                }
            }
#pragma unroll
            for (int mt = 0; mt < 4; mt++)
#pragma unroll
                for (int nt = 0; nt < 8; nt++)
                    mma_tf32(acc[mt][nt], af[mt], bf[nt]);
        }
    }

    // epilogue: float2 stores (c even -> 8B aligned)
#pragma unroll
    for (int mt = 0; mt < 4; mt++) {
        int r = row0 + wM0 + mt * 16 + gid;
#pragma unroll
        for (int nt = 0; nt < 8; nt++) {
            int c = col0 + wN0 + nt * 8 + tig * 2;
            float b0 = 0.f, b1 = 0.f;
            if (bias) { b0 = bias[c]; b1 = bias[c + 1]; }
            float2 v0, v1;
            v0.x = alpha * acc[mt][nt][0] + b0;
            v0.y = alpha * acc[mt][nt][1] + b1;
            v1.x = alpha * acc[mt][nt][2] + b0;
            v1.y = alpha * acc[mt][nt][3] + b1;
            float* p0 = &C[(long)r * ldc + c];
            float* p1 = &C[(long)(r + 8) * ldc + c];
            if (accumulate) {
                float2 o0 = *(const float2*)p0, o1 = *(const float2*)p1;
                v0.x += o0.x; v0.y += o0.y; v1.x += o1.x; v1.y += o1.y;
            }
            if (roundOut) {
                v0.x = tf32r(v0.x); v0.y = tf32r(v0.y);
                v1.x = tf32r(v1.x); v1.y = tf32r(v1.y);
            }
            *(float2*)p0 = v0;
            *(float2*)p1 = v1;
        }
    }
}

// ---------------------------------------------------------------------------
// Single-pass row softmax (L = 1024, 256 threads, float4/thread), output
// tf32-rounded (it feeds the AV GEMM directly).
// ---------------------------------------------------------------------------
__global__ void softmax1(float* __restrict__ S)
{
    float4* p = (float4*)(S + (long)blockIdx.x * 1024);
    int tid = threadIdx.x, lane = tid & 31, wid = tid >> 5;
    __shared__ float red[16];

    float4 v = p[tid];
    float m = fmaxf(fmaxf(v.x, v.y), fmaxf(v.z, v.w));
#pragma unroll
    for (int o = 16; o > 0; o >>= 1) m = fmaxf(m, __shfl_xor_sync(0xffffffffu, m, o));
    if (lane == 0) red[wid] = m;
    __syncthreads();
    m = red[0];
#pragma unroll
    for (int i = 1; i < 8; i++) m = fmaxf(m, red[i]);

    v.x = __expf(v.x - m); v.y = __expf(v.y - m);
    v.z = __expf(v.z - m); v.w = __expf(v.w - m);
    float sum = v.x + v.y + v.z + v.w;
#pragma unroll
    for (int o = 16; o > 0; o >>= 1) sum += __shfl_xor_sync(0xffffffffu, sum, o);
    if (lane == 0) red[8 + wid] = sum;
    __syncthreads();
    sum = red[8];
#pragma unroll
    for (int i = 1; i < 8; i++) sum += red[8 + i];
    float inv = 1.f / sum;

    v.x = tf32r(v.x * inv); v.y = tf32r(v.y * inv);
    v.z = tf32r(v.z * inv); v.w = tf32r(v.w * inv);
    p[tid] = v;
}

// ---------------------------------------------------------------------------
// out = LayerNorm(tmp + res) * g + b ; writes exact (out) and rounded (out_r)
// ---------------------------------------------------------------------------
__global__ void add_ln_kernel(const float* __restrict__ tmp, const float* __restrict__ res,
                              const float* __restrict__ g, const float* __restrict__ b,
                              float* __restrict__ out, float* __restrict__ out_r)
{
    long row = blockIdx.x;
    const float* t = tmp + row * (long)HD;
    const float* r = res + row * (long)HD;
    float* o  = out   + row * (long)HD;
    float* orr = out_r + row * (long)HD;
    __shared__ float red[256];
    int tid = threadIdx.x;

    float v0 = t[tid]       + r[tid];
    float v1 = t[tid + 256] + r[tid + 256];
    red[tid] = v0 + v1; __syncthreads();
    for (int s = 128; s > 0; s >>= 1) { if (tid < s) red[tid] += red[tid + s]; __syncthreads(); }
    float mean = red[0] * (1.f / HD);
    __syncthreads();
    float d0 = v0 - mean, d1 = v1 - mean;
    red[tid] = d0 * d0 + d1 * d1; __syncthreads();
    for (int s = 128; s > 0; s >>= 1) { if (tid < s) red[tid] += red[tid + s]; __syncthreads(); }
    float rstd = rsqrtf(red[0] * (1.f / HD) + 1e-5f);
    float w0 = d0 * rstd * g[tid]       + b[tid];
    float w1 = d1 * rstd * g[tid + 256] + b[tid + 256];
    o[tid]        = w0;
    o[tid + 256]  = w1;
    orr[tid]       = tf32r(w0);
    orr[tid + 256] = tf32r(w1);
}

// ---------------------------------------------------------------------------
// Input projections (dual write: exact + rounded)
// ---------------------------------------------------------------------------
__global__ void proj_in_kernel(const float* __restrict__ cx, const float* __restrict__ cy,
                               const float* __restrict__ W, const float* __restrict__ bias,
                               float* __restrict__ out, float* __restrict__ out_r, int j)
{
    int idx = blockIdx.x * blockDim.x + threadIdx.x;
    if (idx >= RR * HD) return;
    int r = idx >> 9;
    int h = idx & (HD - 1);
    float x0 = cx[r];
    float y0 = cy[r * 8 + j * 2];
    float y1 = cy[r * 8 + j * 2 + 1];
    float v = x0 * W[h] + y0 * W[HD + h] + y1 * W[2 * HD + h] + bias[h];
    out[idx]   = v;
    out_r[idx] = tf32r(v);
}

__global__ void proj1_kernel(const float* __restrict__ x, const float* __restrict__ W,
                             const float* __restrict__ bias,
                             float* __restrict__ out, float* __restrict__ out_r)
{
    int idx = blockIdx.x * blockDim.x + threadIdx.x;
    if (idx >= RR * HD) return;
    int r = idx >> 9;
    int h = idx & (HD - 1);
    float v = x[r] * W[h] + bias[h];
    out[idx]   = v;
    out_r[idx] = tf32r(v);
}

// ---------------------------------------------------------------------------
// Weight prep: pack K|V|Q into fused 512x1536 (rounded); round Wf.
// ---------------------------------------------------------------------------
__global__ void pack_qkv_kernel(const float* __restrict__ Wk, const float* __restrict__ Wv,
                                const float* __restrict__ Wq, float* __restrict__ dst)
{
    int i = blockIdx.x * blockDim.x + threadIdx.x;
    if (i >= 512 * 512) return;
    int k = i >> 9, n = i & 511;
    float* d = dst + (long)k * QW;
    d[n]        = tf32r(Wk[i]);
    d[512 + n]  = tf32r(Wv[i]);
    d[1024 + n] = tf32r(Wq[i]);
}

__global__ void round_kernel(const float* __restrict__ in, float* __restrict__ out, int n)
{
    int i = blockIdx.x * blockDim.x + threadIdx.x;
    if (i < n) out[i] = tf32r(in[i]);
}

// ---------------------------------------------------------------------------
// Host-side orchestration
// ---------------------------------------------------------------------------
static inline void gemm(bool transB, const float* A, const float* B, float* C, const float* bias,
                        int M, int N, int K, int lda, int ldb, int ldc,
                        long sAb, long sAh, long sBb, long sBh, long sCb, long sCh,
                        int nb, int nh, float alpha, int acc, int rnd)
{
    dim3 grid(N / 128, M / 128, nb * nh);
    if (transB)
        gemm_tc<true><<<grid, 128>>>(A, B, C, bias, K, lda, ldb, ldc,
                                     sAb, sAh, sBb, sBh, sCb, sCh, nh, alpha, acc, rnd);
    else
        gemm_tc<false><<<grid, 128>>>(A, B, C, bias, K, lda, ldb, ldc,
                                      sAb, sAh, sBb, sBh, sCb, sCh, nh, alpha, acc, rnd);
}

struct Bufs {
    float *e, *e1, *e2, *e3, *er, *qb, *qbr, *kbr, *R, *T, *QKV, *QKV2, *S, *Wc, *Wf;
};

// Encoder self/cross layer. x: exact state; xr: rounded; x2r: rounded domain input.
static void sc_attn(Bufs& Z, float* x, float* xr, const float* x2r, bool same,
                    const float* Wc, const float* WfR, const float* bf,
                    const float* gg, const float* bb)
{
    const int hn = 2, d = 256, Nn = 1024, Bb = 4;
    const float scale = rsqrtf((float)d);

    // fused QKV -> [K|V|Q] in 1536-wide rows
    gemm(false, xr, Wc, Z.QKV, nullptr, RR, QW, HD, HD, QW, QW,
         0,0,0,0,0,0, 1,1, 1.f, 0, 1);
    if (!same)
        gemm(false, x2r, Wc, Z.QKV2, nullptr, RR, QW, HD, HD, QW, QW,
             0,0,0,0,0,0, 1,1, 1.f, 0, 1);

    const float* b1 = Z.QKV;
    const float* b2 = same ? Z.QKV : Z.QKV2;
    const float* Qb[4] = { b1 + 1024, b2 + 1024, b2 + 1024, b1 + 1024 };
    const float* Kb[4] = { b1,        b2,        b1,        b2 };
    const float* Vb[4] = { b1 + 512,  b2 + 512,  b1 + 512,  b2 + 512 };
    int   ncomb = same ? 1 : 4;
    float av    = same ? 4.f : 1.f;

    for (int c = 0; c < ncomb; c++) {
        gemm(true, Qb[c], Kb[c], Z.S, nullptr,
             Nn, Nn, d, QW, QW, Nn,
             (long)Nn * QW, d, (long)Nn * QW, d, (long)hn * Nn * Nn, (long)Nn * Nn,
             Bb, hn, scale, 0, 0);
        softmax1<<<Bb * hn * Nn, 256>>>(Z.S);
        gemm(false, Z.S, Vb[c], Z.R, nullptr,
             Nn, d, Nn, Nn, QW, HD,
             (long)hn * Nn * Nn, (long)Nn * Nn, (long)Nn * QW, d, (long)Nn * HD, d,
             Bb, hn, av, c > 0, c == ncomb - 1);
    }

    gemm(false, xr,  WfR,               Z.T, bf,      RR, HD, HD, HD, HD, HD,
         0,0,0,0,0,0, 1,1, 1.f, 0, 0);
    gemm(false, Z.R, WfR + 512 * 512,   Z.T, nullptr, RR, HD, HD, HD, HD, HD,
         0,0,0,0,0,0, 1,1, 1.f, 1, 0);

    add_ln_kernel<<<RR, 256>>>(Z.T, x, gg, bb, x, xr);
}

// Decoder cross-attn layer (h=4, d=128).
static void cross_attn(Bufs& Z, float* qv, float* qvr, const float* kvr, const float* evr,
                       const float* Wc, const float* WfR, const float* bf,
                       const float* gg, const float* bb)
{
    const int hn = 4, d = 128, Nn = 1024, Bb = 4;
    const float scale = rsqrtf((float)d);

    // QKV into the fused activation buffer (separate A per projection)
    gemm(false, kvr, Wc,        Z.QKV,        nullptr, RR, 512, HD, HD, QW, QW,
         0,0,0,0,0,0, 1,1, 1.f, 0, 1);                                   // K -> cols 0..511
    gemm(false, evr, Wc + 512,  Z.QKV + 512,  nullptr, RR, 512, HD, HD, QW, QW,
         0,0,0,0,0,0, 1,1, 1.f, 0, 1);                                   // V -> cols 512..1023
    gemm(false, qvr, Wc + 1024, Z.QKV + 1024, nullptr, RR, 512, HD, HD, QW, QW,
         0,0,0,0,0,0, 1,1, 1.f, 0, 1);                                   // Q -> cols 1024..1535

    gemm(true, Z.QKV + 1024, Z.QKV, Z.S, nullptr,
         Nn, Nn, d, QW, QW, Nn,
         (long)Nn * QW, d, (long)Nn * QW, d, (long)hn * Nn * Nn, (long)Nn * Nn,
         Bb, hn, scale, 0, 0);
    softmax1<<<Bb * hn * Nn, 256>>>(Z.S);
    gemm(false, Z.S, Z.QKV + 512, Z.R, nullptr,
         Nn, d, Nn, Nn, QW, HD,
         (long)hn * Nn * Nn, (long)Nn * Nn, (long)Nn * QW, d, (long)Nn * HD, d,
         Bb, hn, 1.f, 0, 1);

    gemm(false, qvr, WfR,             Z.T, bf,      RR, HD, HD, HD, HD, HD,
         0,0,0,0,0,0, 1,1, 1.f, 0, 0);
    gemm(false, Z.R, WfR + 512 * 512, Z.T, nullptr, RR, HD, HD, HD, HD, HD,
         0,0,0,0,0,0, 1,1, 1.f, 1, 0);

    add_ln_kernel<<<RR, 256>>>(Z.T, qv, gg, bb, qv, qvr);
}

extern "C" void kernel_launch(void* const* d_in, const int* in_sizes, int n_in,
                              void* d_out, int out_size)
{
    const float* context_x = (const float*)d_in[0];
    const float* context_y = (const float*)d_in[1];
    const float* target_x  = (const float*)d_in[2];
    const float* in_W = (const float*)d_in[3];
    const float* in_b = (const float*)d_in[4];
    const float* cx_W = (const float*)d_in[5];
    const float* cx_b = (const float*)d_in[6];
    const float* tx_W = (const float*)d_in[7];
    const float* tx_b = (const float*)d_in[8];
    const float* sc_Wk = (const float*)d_in[9];
    const float* sc_Wv = (const float*)d_in[10];
    const float* sc_Wq = (const float*)d_in[11];
    const float* sc_Wf = (const float*)d_in[12];
    const float* sc_bf = (const float*)d_in[13];
    const float* sc_g  = (const float*)d_in[14];
    const float* sc_b  = (const float*)d_in[15];
    const float* ca_Wk = (const float*)d_in[16];
    const float* ca_Wv = (const float*)d_in[17];
    const float* ca_Wq = (const float*)d_in[18];
    const float* ca_Wf = (const float*)d_in[19];
    const float* ca_bf = (const float*)d_in[20];
    const float* ca_g  = (const float*)d_in[21];
    const float* ca_b  = (const float*)d_in[22];

    Bufs Z;
    cudaGetSymbolAddress((void**)&Z.e,    g_e);
    cudaGetSymbolAddress((void**)&Z.e1,   g_e1);
    cudaGetSymbolAddress((void**)&Z.e2,   g_e2);
    cudaGetSymbolAddress((void**)&Z.e3,   g_e3);
    cudaGetSymbolAddress((void**)&Z.er,   g_er);
    cudaGetSymbolAddress((void**)&Z.qb,   g_qb);
    cudaGetSymbolAddress((void**)&Z.qbr,  g_qbr);
    cudaGetSymbolAddress((void**)&Z.kbr,  g_kbr);
    cudaGetSymbolAddress((void**)&Z.R,    g_R);
    cudaGetSymbolAddress((void**)&Z.T,    g_T);
    cudaGetSymbolAddress((void**)&Z.QKV,  g_QKV);
    cudaGetSymbolAddress((void**)&Z.QKV2, g_QKV2);
    cudaGetSymbolAddress((void**)&Z.S,    g_S);
    cudaGetSymbolAddress((void**)&Z.Wc,   g_Wc);
    cudaGetSymbolAddress((void**)&Z.Wf,   g_Wf);

    const long WW  = (long)HD * HD;        // 512*512 per-layer stride (Wk/Wv/Wq)
    const long WFL = (long)512 * 1024;     // per-layer Wf element count
    const long WCL = (long)512 * QW;       // fused weight per-layer size

    // ---- weight prep (rounded / packed) ----
    {
        int n = 512 * 512, nb = (n + 255) / 256;
        for (int i = 0; i < 2; i++) {
            pack_qkv_kernel<<<nb, 256>>>(sc_Wk + i * WW, sc_Wv + i * WW, sc_Wq + i * WW,
                                         Z.Wc + i * WCL);
            pack_qkv_kernel<<<nb, 256>>>(ca_Wk + i * WW, ca_Wv + i * WW, ca_Wq + i * WW,
                                         Z.Wc + (2 + i) * WCL);
        }
        int nf = 2 * 1024 * 512, nbf = (nf + 255) / 256;
        round_kernel<<<nbf, 256>>>(sc_Wf, Z.Wf, nf);
        round_kernel<<<nbf, 256>>>(ca_Wf, Z.Wf + nf, nf);
    }

    const int nthr = 256, nblk = (RR * HD + nthr - 1) / nthr;

    // ---- input projections ----
    proj_in_kernel<<<nblk, nthr>>>(context_x, context_y, in_W, in_b, Z.e,  Z.er, 0);
    proj_in_kernel<<<nblk, nthr>>>(context_x, context_y, in_W, in_b, Z.e1, Z.e1, 1);
    proj_in_kernel<<<nblk, nthr>>>(context_x, context_y, in_W, in_b, Z.e2, Z.e2, 2);
    proj_in_kernel<<<nblk, nthr>>>(context_x, context_y, in_W, in_b, Z.e3, Z.e3, 3);

    // ---- encoder ----
    for (int i = 0; i < 2; i++)
        sc_attn(Z, Z.e, Z.er, Z.er, true,
                Z.Wc + i * WCL, Z.Wf + i * WFL,
                sc_bf + i * HD, sc_g + i * HD, sc_b + i * HD);

    const float* xs2[3] = { Z.e1, Z.e2, Z.e3 };
    for (int s = 0; s < 3; s++)
        for (int i = 0; i < 2; i++)
            sc_attn(Z, Z.e, Z.er, xs2[s], false,
                    Z.Wc + i * WCL, Z.Wf + i * WFL,
                    sc_bf + i * HD, sc_g + i * HD, sc_b + i * HD);

    // ---- decoder inputs ----
    proj1_kernel<<<nblk, nthr>>>(target_x,  tx_W, tx_b, Z.qb,  Z.qbr);
    proj1_kernel<<<nblk, nthr>>>(context_x, cx_W, cx_b, Z.kbr, Z.kbr);

    // ---- decoder ----
    for (int i = 0; i < 2; i++)
        cross_attn(Z, Z.qb, Z.qbr, Z.kbr, Z.er,
                   Z.Wc + (2 + i) * WCL, Z.Wf + 2 * WFL + i * WFL,
                   ca_bf + i * HD, ca_g + i * HD, ca_b + i * HD);

    cudaMemcpyAsync(d_out, Z.qb, (size_t)RR * HD * sizeof(float),
                    cudaMemcpyDeviceToDevice);
}

// round 9
// speedup vs baseline: 8.4286x; 2.0338x over previous
#include <cuda_runtime.h>
#include <cuda_fp16.h>
#include <math.h>
#include <stdint.h>

// ---------------------------------------------------------------------------
// MultidomainEncoder: B=4, N=M=1024, H=512.
// Round 6: fp16 mma.sync m16n8k16 GEMM (fp32 accum), all-transB operands,
// cp.async double buffering, conflict-free half smem, batched SDPA combos.
// ---------------------------------------------------------------------------

#define RR   4096          // B*N == B*M rows
#define HD   512           // model dim
#define QW   1536          // fused QKV row width

__device__ float  g_e   [RR * HD];                  // exact encoder state
__device__ __half g_er  [RR * HD];                  // fp16 operand copy of e
__device__ __half g_e1  [RR * HD];
__device__ __half g_e2  [RR * HD];
__device__ __half g_e3  [RR * HD];
__device__ float  g_qb  [RR * HD];
__device__ __half g_qbr [RR * HD];
__device__ __half g_kbr [RR * HD];
__device__ __half g_R   [RR * HD];
__device__ float  g_T   [RR * HD];
__device__ __half g_QKV [2 * (size_t)RR * QW];      // two fused QKV buffers
__device__ __half g_Vt  [2 * (size_t)8 * 256 * 1024];
__device__ float  g_R4  [(size_t)RR * 2048];        // per-combo AV outputs (cross)
__device__ float  g_S   [(size_t)32 * 1024 * 1024]; // pre-softmax scores (fp32)
__device__ __half g_S16 [(size_t)32 * 1024 * 1024]; // post-softmax probs (fp16)
__device__ __half g_Wc  [4 * (size_t)QW * 512];     // transposed fused QKV weights
__device__ __half g_Wf  [8 * (size_t)512 * 512];    // transposed Wf chunks

// ---------------------------------------------------------------------------
// helpers
// ---------------------------------------------------------------------------
__device__ __forceinline__ void mma_f16(float c[4], const uint32_t a[4], const uint32_t b[2]) {
    asm volatile(
        "mma.sync.aligned.m16n8k16.row.col.f32.f16.f16.f32 "
        "{%0,%1,%2,%3}, {%4,%5,%6,%7}, {%8,%9}, {%0,%1,%2,%3};"
        : "+f"(c[0]), "+f"(c[1]), "+f"(c[2]), "+f"(c[3])
        : "r"(a[0]), "r"(a[1]), "r"(a[2]), "r"(a[3]), "r"(b[0]), "r"(b[1]));
}

__device__ __forceinline__ void cp16(uint32_t* dst, const void* src) {
    uint32_t d = (uint32_t)__cvta_generic_to_shared(dst);
    asm volatile("cp.async.cg.shared.global [%0], [%1], 16;" :: "r"(d), "l"(src));
}
#define CP_COMMIT() asm volatile("cp.async.commit_group;" ::: "memory")
#define CP_WAIT1()  asm volatile("cp.async.wait_group 1;"  ::: "memory")
#define CP_WAIT0()  asm volatile("cp.async.wait_group 0;"  ::: "memory")

struct Offs { long a[4]; long b[4]; long c[4]; };

// ---------------------------------------------------------------------------
// fp16 GEMM:  C[m,n] = alpha * sum_k A[m,k] * B[n,k]  [+bias] [+C]
// A: [M,K] row-major fp16 (lda); B: [N,K] row-major fp16 (ldb).
// C: fp32 (outHalf=0, supports bias/accumulate) or fp16 (outHalf=1).
// Tile 128x128x32, 256 threads (8 warps, warp tile 64x32), cp.async 2-stage.
// M, N multiples of 128; K multiple of 32. Batched z = combo*nzc + b*nh + h.
// smem row pitch 20 words: lanes (gid,tig) -> bank gid*20+tig (all distinct).
// ---------------------------------------------------------------------------
#define WPR 20   // words per smem row (16 data + 4 pad)

__global__ void __launch_bounds__(256)
gemm_h(const __half* __restrict__ A, const __half* __restrict__ B,
       void* __restrict__ Cv, const float* __restrict__ bias,
       int K, int lda, int ldb, int ldc,
       long sAb, long sAh, long sBb, long sBh, long sCb, long sCh,
       int nh, int nzc, Offs off, float alpha, int accumulate, int outHalf)
{
    __shared__ uint32_t sA[2][128 * WPR];
    __shared__ uint32_t sB[2][128 * WPR];

    int z   = blockIdx.z;
    int cmb = z / nzc;
    int inn = z - cmb * nzc;
    int bb  = inn / nh;
    int hh  = inn - bb * nh;
    A += off.a[cmb] + (long)bb * sAb + (long)hh * sAh;
    B += off.b[cmb] + (long)bb * sBb + (long)hh * sBh;
    long coff = off.c[cmb] + (long)bb * sCb + (long)hh * sCh;

    const int row0 = blockIdx.y * 128;
    const int col0 = blockIdx.x * 128;
    const int tid  = threadIdx.x;
    const int wid  = tid >> 5;
    const int lane = tid & 31;
    const int wM0 = (wid & 1) * 64;
    const int wN0 = (wid >> 1) * 32;
    const int gid = lane >> 2;
    const int tig = lane & 3;

    float acc[4][4][4] = {};

    const int lrow = tid >> 1;          // 0..127
    const int lsel = tid & 1;           // half-row selector

    auto loadTile = [&](int t, int s) {
        const __half* ga = A + (long)(row0 + lrow) * lda + t * 32 + lsel * 16;
        const __half* gb = B + (long)(col0 + lrow) * ldb + t * 32 + lsel * 16;
        uint32_t* sa = &sA[s][lrow * WPR + lsel * 8];
        uint32_t* sb = &sB[s][lrow * WPR + lsel * 8];
        cp16(sa, ga); cp16(sa + 4, ga + 8);
        cp16(sb, gb); cp16(sb + 4, gb + 8);
    };

    const int nT = K / 32;
    loadTile(0, 0);
    CP_COMMIT();

    for (int t = 0; t < nT; t++) {
        int s = t & 1;
        if (t + 1 < nT) {
            loadTile(t + 1, s ^ 1);
            CP_COMMIT();
            CP_WAIT1();
        } else {
            CP_WAIT0();
        }
        __syncthreads();

        const uint32_t* Ap = sA[s];
        const uint32_t* Bp = sB[s];
#pragma unroll
        for (int ko = 0; ko < 16; ko += 8) {
            uint32_t af[4][4], bfr[4][2];
#pragma unroll
            for (int mt = 0; mt < 4; mt++) {
                int m = wM0 + mt * 16 + gid;
                af[mt][0] = Ap[m * WPR + ko + tig];
                af[mt][1] = Ap[(m + 8) * WPR + ko + tig];
                af[mt][2] = Ap[m * WPR + ko + 4 + tig];
                af[mt][3] = Ap[(m + 8) * WPR + ko + 4 + tig];
            }
#pragma unroll
            for (int nt = 0; nt < 4; nt++) {
                int n = wN0 + nt * 8 + gid;
                bfr[nt][0] = Bp[n * WPR + ko + tig];
                bfr[nt][1] = Bp[n * WPR + ko + 4 + tig];
            }
#pragma unroll
            for (int mt = 0; mt < 4; mt++)
#pragma unroll
                for (int nt = 0; nt < 4; nt++)
                    mma_f16(acc[mt][nt], af[mt], bfr[nt]);
        }
        __syncthreads();
    }

    // ---- epilogue ----
    if (!outHalf) {
        float* C = (float*)Cv + coff;
#pragma unroll
        for (int mt = 0; mt < 4; mt++) {
            int r = row0 + wM0 + mt * 16 + gid;
#pragma unroll
            for (int nt = 0; nt < 4; nt++) {
                int c = col0 + wN0 + nt * 8 + tig * 2;
                float b0 = 0.f, b1 = 0.f;
                if (bias) { b0 = bias[c]; b1 = bias[c + 1]; }
                float2 v0, v1;
                v0.x = alpha * acc[mt][nt][0] + b0;
                v0.y = alpha * acc[mt][nt][1] + b1;
                v1.x = alpha * acc[mt][nt][2] + b0;
                v1.y = alpha * acc[mt][nt][3] + b1;
                float* p0 = &C[(long)r * ldc + c];
                float* p1 = &C[(long)(r + 8) * ldc + c];
                if (accumulate) {
                    float2 o0 = *(const float2*)p0, o1 = *(const float2*)p1;
                    v0.x += o0.x; v0.y += o0.y; v1.x += o1.x; v1.y += o1.y;
                }
                *(float2*)p0 = v0;
                *(float2*)p1 = v1;
            }
        }
    } else {
        __half* C = (__half*)Cv + coff;
#pragma unroll
        for (int mt = 0; mt < 4; mt++) {
            int r = row0 + wM0 + mt * 16 + gid;
#pragma unroll
            for (int nt = 0; nt < 4; nt++) {
                int c = col0 + wN0 + nt * 8 + tig * 2;
                __half2 h0 = __floats2half2_rn(alpha * acc[mt][nt][0], alpha * acc[mt][nt][1]);
                __half2 h1 = __floats2half2_rn(alpha * acc[mt][nt][2], alpha * acc[mt][nt][3]);
                *(__half2*)&C[(long)r * ldc + c]       = h0;
                *(__half2*)&C[(long)(r + 8) * ldc + c] = h1;
            }
        }
    }
}

// ---------------------------------------------------------------------------
// Single-pass row softmax (L=1024): fp32 in, fp16 out.
// ---------------------------------------------------------------------------
__global__ void softmax1(const float* __restrict__ S, __half* __restrict__ S16)
{
    const float4* p = (const float4*)(S + (long)blockIdx.x * 1024);
    __half2* o = (__half2*)(S16 + (long)blockIdx.x * 1024);
    int tid = threadIdx.x, lane = tid & 31, wid = tid >> 5;
    __shared__ float red[16];

    float4 v = p[tid];
    float m = fmaxf(fmaxf(v.x, v.y), fmaxf(v.z, v.w));
#pragma unroll
    for (int t = 16; t > 0; t >>= 1) m = fmaxf(m, __shfl_xor_sync(0xffffffffu, m, t));
    if (lane == 0) red[wid] = m;
    __syncthreads();
    m = red[0];
#pragma unroll
    for (int i = 1; i < 8; i++) m = fmaxf(m, red[i]);

    v.x = __expf(v.x - m); v.y = __expf(v.y - m);
    v.z = __expf(v.z - m); v.w = __expf(v.w - m);
    float sum = v.x + v.y + v.z + v.w;
#pragma unroll
    for (int t = 16; t > 0; t >>= 1) sum += __shfl_xor_sync(0xffffffffu, sum, t);
    if (lane == 0) red[8 + wid] = sum;
    __syncthreads();
    sum = red[8];
#pragma unroll
    for (int i = 1; i < 8; i++) sum += red[8 + i];
    float inv = 1.f / sum;

    o[2 * tid]     = __floats2half2_rn(v.x * inv, v.y * inv);
    o[2 * tid + 1] = __floats2half2_rn(v.z * inv, v.w * inv);
}

// ---------------------------------------------------------------------------
// fold (cross layers): R[row,col] = fp16( sum_{c<4} R4[row, c*512+col] )
// ---------------------------------------------------------------------------
__global__ void fold_kernel(const float* __restrict__ R4, __half* __restrict__ R)
{
    int idx = blockIdx.x * blockDim.x + threadIdx.x;
    if (idx >= RR * HD) return;
    int row = idx >> 9, col = idx & 511;
    const float* p = R4 + (long)row * 2048 + col;
    R[idx] = __float2half_rn(p[0] + p[512] + p[1024] + p[1536]);
}

// ---------------------------------------------------------------------------
// transpose V head-slices: src [4*1024 rows, ld] cols [512 + h*d, +d)
//  -> dst [b*hn+h][d][1024]   (fp16)
// ---------------------------------------------------------------------------
__global__ void transpose_v(const __half* __restrict__ src, __half* __restrict__ dst,
                            int ld, int d, int hn)
{
    __shared__ __half t[32][34];
    int z = blockIdx.z;
    int b = z / hn, h = z - b * hn;
    int m0 = blockIdx.x * 32, c0 = blockIdx.y * 32;
    const __half* s = src + (long)(b * 1024) * ld + 512 + h * d;
    int tx = threadIdx.x, ty = threadIdx.y;
#pragma unroll
    for (int i = 0; i < 4; i++)
        t[ty + i * 8][tx] = s[(long)(m0 + ty + i * 8) * ld + c0 + tx];
    __syncthreads();
    __half* o = dst + (long)z * d * 1024;
#pragma unroll
    for (int i = 0; i < 4; i++)
        o[(long)(c0 + ty + i * 8) * 1024 + m0 + tx] = t[tx][ty + i * 8];
}

// ---------------------------------------------------------------------------
// out = LayerNorm(tmp + res) * g + b ; writes exact fp32 + fp16 operand copy
// ---------------------------------------------------------------------------
__global__ void add_ln_kernel(const float* __restrict__ tmp, const float* __restrict__ res,
                              const float* __restrict__ g, const float* __restrict__ b,
                              float* __restrict__ out, __half* __restrict__ outh)
{
    long row = blockIdx.x;
    const float* t = tmp + row * (long)HD;
    const float* r = res + row * (long)HD;
    float* o = out + row * (long)HD;
    __half* oh = outh + row * (long)HD;
    __shared__ float red[256];
    int tid = threadIdx.x;

    float v0 = t[tid]       + r[tid];
    float v1 = t[tid + 256] + r[tid + 256];
    red[tid] = v0 + v1; __syncthreads();
    for (int s = 128; s > 0; s >>= 1) { if (tid < s) red[tid] += red[tid + s]; __syncthreads(); }
    float mean = red[0] * (1.f / HD);
    __syncthreads();
    float d0 = v0 - mean, d1 = v1 - mean;
    red[tid] = d0 * d0 + d1 * d1; __syncthreads();
    for (int s = 128; s > 0; s >>= 1) { if (tid < s) red[tid] += red[tid + s]; __syncthreads(); }
    float rstd = rsqrtf(red[0] * (1.f / HD) + 1e-5f);
    float w0 = d0 * rstd * g[tid]       + b[tid];
    float w1 = d1 * rstd * g[tid + 256] + b[tid + 256];
    o[tid]       = w0;
    o[tid + 256] = w1;
    oh[tid]       = __float2half_rn(w0);
    oh[tid + 256] = __float2half_rn(w1);
}

// ---------------------------------------------------------------------------
// Input projections
// ---------------------------------------------------------------------------
__global__ void proj_in_kernel(const float* __restrict__ cx, const float* __restrict__ cy,
                               const float* __restrict__ W, const float* __restrict__ bias,
                               float* __restrict__ out, __half* __restrict__ outh, int j)
{
    int idx = blockIdx.x * blockDim.x + threadIdx.x;
    if (idx >= RR * HD) return;
    int r = idx >> 9;
    int h = idx & (HD - 1);
    float x0 = cx[r];
    float y0 = cy[r * 8 + j * 2];
    float y1 = cy[r * 8 + j * 2 + 1];
    float v = x0 * W[h] + y0 * W[HD + h] + y1 * W[2 * HD + h] + bias[h];
    if (out) out[idx] = v;
    outh[idx] = __float2half_rn(v);
}

__global__ void proj1_kernel(const float* __restrict__ x, const float* __restrict__ W,
                             const float* __restrict__ bias,
                             float* __restrict__ out, __half* __restrict__ outh)
{
    int idx = blockIdx.x * blockDim.x + threadIdx.x;
    if (idx >= RR * HD) return;
    int r = idx >> 9;
    int h = idx & (HD - 1);
    float v = x[r] * W[h] + bias[h];
    if (out) out[idx] = v;
    outh[idx] = __float2half_rn(v);
}

// ---------------------------------------------------------------------------
// Weight prep: transposed+fp16. Wct rows [K|V|Q], each [n][k].
// ---------------------------------------------------------------------------
__global__ void pack_qkv_t(const float* __restrict__ Wk, const float* __restrict__ Wv,
                           const float* __restrict__ Wq, __half* __restrict__ dst)
{
    int i = blockIdx.x * blockDim.x + threadIdx.x;
    if (i >= 512 * 512) return;
    int k = i >> 9, n = i & 511;
    dst[(long)n * 512 + k]          = __float2half_rn(Wk[i]);
    dst[(long)(512 + n) * 512 + k]  = __float2half_rn(Wv[i]);
    dst[(long)(1024 + n) * 512 + k] = __float2half_rn(Wq[i]);
}

__global__ void wf_t_kernel(const float* __restrict__ Wf,
                            __half* __restrict__ d1, __half* __restrict__ d2)
{
    int i = blockIdx.x * blockDim.x + threadIdx.x;
    if (i >= 512 * 512) return;
    int k = i >> 9, n = i & 511;
    d1[(long)n * 512 + k] = __float2half_rn(Wf[(long)k * 512 + n]);
    d2[(long)n * 512 + k] = __float2half_rn(Wf[(long)(512 + k) * 512 + n]);
}

// ---------------------------------------------------------------------------
// Host orchestration
// ---------------------------------------------------------------------------
static void gemmH(const __half* A, const __half* B, void* C, const float* bias,
                  int M, int N, int K, int lda, int ldb, int ldc,
                  long sAb, long sAh, long sBb, long sBh, long sCb, long sCh,
                  int nb, int nh, int ncomb, const Offs& off,
                  float alpha, int acc, int outHalf)
{
    dim3 grid(N / 128, M / 128, ncomb * nb * nh);
    gemm_h<<<grid, 256>>>(A, B, C, bias, K, lda, ldb, ldc,
                          sAb, sAh, sBb, sBh, sCb, sCh,
                          nh, nb * nh, off, alpha, acc, outHalf);
}

struct Bufs {
    float *e, *qb, *T, *R4, *S;
    __half *er, *e1, *e2, *e3, *qbr, *kbr, *R, *QKV, *Vt, *S16, *Wc, *Wf;
};

static const long QBUF  = (long)RR * QW;           // QKV buffer stride (halfs)
static const long VTSZ  = (long)8 * 256 * 1024;    // Vt buffer stride (halfs)
static const long SSEG  = (long)8 * 1024 * 1024;   // S segment per combo

// Encoder self/cross layer.
static void sc_attn(Bufs& Z, float* x, __half* xr, const __half* x2r, bool same,
                    const __half* Wct, const __half* Wf1, const __half* Wf2,
                    const float* bf, const float* gg, const float* bb)
{
    const float scale = rsqrtf(256.f);
    Offs z0 = {};

    // fused QKV -> [K|V|Q] fp16
    gemmH(xr, Wct, Z.QKV, nullptr, RR, QW, HD, HD, HD, QW,
          0,0,0,0,0,0, 1,1,1, z0, 1.f, 0, 1);
    if (!same)
        gemmH(x2r, Wct, Z.QKV + QBUF, nullptr, RR, QW, HD, HD, HD, QW,
              0,0,0,0,0,0, 1,1,1, z0, 1.f, 0, 1);

    transpose_v<<<dim3(32, 8, 8), dim3(32, 8)>>>(Z.QKV, Z.Vt, QW, 256, 2);
    if (!same)
        transpose_v<<<dim3(32, 8, 8), dim3(32, 8)>>>(Z.QKV + QBUF, Z.Vt + VTSZ, QW, 256, 2);

    const long selQ[4] = {0, 1, 1, 0};
    const long selK[4] = {0, 1, 0, 1};
    const long selV[4] = {0, 1, 0, 1};
    int ncomb = same ? 1 : 4;

    Offs oQK = {}, oAV = {};
    for (int c = 0; c < 4; c++) {
        oQK.a[c] = selQ[c] * QBUF + 1024;
        oQK.b[c] = selK[c] * QBUF;
        oQK.c[c] = c * SSEG;
        oAV.a[c] = c * SSEG;
        oAV.b[c] = selV[c] * VTSZ;
        oAV.c[c] = c * 512;
    }

    // batched QK -> S fp32
    gemmH(Z.QKV, Z.QKV, Z.S, nullptr, 1024, 1024, 256, QW, QW, 1024,
          (long)1024 * QW, 256, (long)1024 * QW, 256,
          (long)2 * 1024 * 1024, (long)1024 * 1024,
          4, 2, ncomb, oQK, scale, 0, 0);

    softmax1<<<ncomb * 8 * 1024, 256>>>(Z.S, Z.S16);

    if (same) {
        // single combo: AV straight to R (fp16), alpha = 4
        Offs oAVs = {}; oAVs.b[0] = 0;
        gemmH(Z.S16, Z.Vt, Z.R, nullptr, 1024, 256, 1024, 1024, 1024, 512,
              (long)2 * 1024 * 1024, (long)1024 * 1024,
              (long)2 * 256 * 1024, (long)256 * 1024,
              (long)1024 * 512, 256,
              4, 2, 1, oAVs, 4.f, 0, 1);
    } else {
        // 4 combos -> R4 fp32 column segments, then fold
        gemmH(Z.S16, Z.Vt, Z.R4, nullptr, 1024, 256, 1024, 1024, 1024, 2048,
              (long)2 * 1024 * 1024, (long)1024 * 1024,
              (long)2 * 256 * 1024, (long)256 * 1024,
              (long)1024 * 2048, 256,
              4, 2, 4, oAV, 1.f, 0, 0);
        fold_kernel<<<(RR * HD + 255) / 256, 256>>>(Z.R4, Z.R);
    }

    gemmH(xr,  Wf1, Z.T, bf,      RR, HD, HD, HD, HD, HD, 0,0,0,0,0,0, 1,1,1, z0, 1.f, 0, 0);
    gemmH(Z.R, Wf2, Z.T, nullptr, RR, HD, HD, HD, HD, HD, 0,0,0,0,0,0, 1,1,1, z0, 1.f, 1, 0);

    add_ln_kernel<<<RR, 256>>>(Z.T, x, gg, bb, x, xr);
}

// Decoder cross-attn layer (h=4, d=128).
static void cross_attn(Bufs& Z, float* qv, __half* qvr, const __half* kvr, const __half* evr,
                       const __half* Wct, const __half* Wf1, const __half* Wf2,
                       const float* bf, const float* gg, const float* bb)
{
    const float scale = rsqrtf(128.f);
    Offs z0 = {};

    gemmH(kvr, Wct,              Z.QKV,        nullptr, RR, 512, HD, HD, HD, QW,
          0,0,0,0,0,0, 1,1,1, z0, 1.f, 0, 1);
    gemmH(evr, Wct + 512 * 512,  Z.QKV + 512,  nullptr, RR, 512, HD, HD, HD, QW,
          0,0,0,0,0,0, 1,1,1, z0, 1.f, 0, 1);
    gemmH(qvr, Wct + 1024 * 512, Z.QKV + 1024, nullptr, RR, 512, HD, HD, HD, QW,
          0,0,0,0,0,0, 1,1,1, z0, 1.f, 0, 1);

    transpose_v<<<dim3(32, 4, 16), dim3(32, 8)>>>(Z.QKV, Z.Vt, QW, 128, 4);

    Offs oQK = {}; oQK.a[0] = 1024;
    gemmH(Z.QKV, Z.QKV, Z.S, nullptr, 1024, 1024, 128, QW, QW, 1024,
          (long)1024 * QW, 128, (long)1024 * QW, 128,
          (long)4 * 1024 * 1024, (long)1024 * 1024,
          4, 4, 1, oQK, scale, 0, 0);

    softmax1<<<16 * 1024, 256>>>(Z.S, Z.S16);

    Offs oAV = {};
    gemmH(Z.S16, Z.Vt, Z.R, nullptr, 1024, 128, 1024, 1024, 1024, 512,
          (long)4 * 1024 * 1024, (long)1024 * 1024,
          (long)4 * 128 * 1024, (long)128 * 1024,
          (long)1024 * 512, 128,
          4, 4, 1, oAV, 1.f, 0, 1);

    gemmH(qvr, Wf1, Z.T, bf,      RR, HD, HD, HD, HD, HD, 0,0,0,0,0,0, 1,1,1, z0, 1.f, 0, 0);
    gemmH(Z.R, Wf2, Z.T, nullptr, RR, HD, HD, HD, HD, HD, 0,0,0,0,0,0, 1,1,1, z0, 1.f, 1, 0);

    add_ln_kernel<<<RR, 256>>>(Z.T, qv, gg, bb, qv, qvr);
}

extern "C" void kernel_launch(void* const* d_in, const int* in_sizes, int n_in,
                              void* d_out, int out_size)
{
    const float* context_x = (const float*)d_in[0];
    const float* context_y = (const float*)d_in[1];
    const float* target_x  = (const float*)d_in[2];
    const float* in_W = (const float*)d_in[3];
    const float* in_b = (const float*)d_in[4];
    const float* cx_W = (const float*)d_in[5];
    const float* cx_b = (const float*)d_in[6];
    const float* tx_W = (const float*)d_in[7];
    const float* tx_b = (const float*)d_in[8];
    const float* sc_Wk = (const float*)d_in[9];
    const float* sc_Wv = (const float*)d_in[10];
    const float* sc_Wq = (const float*)d_in[11];
    const float* sc_Wf = (const float*)d_in[12];
    const float* sc_bf = (const float*)d_in[13];
    const float* sc_g  = (const float*)d_in[14];
    const float* sc_b  = (const float*)d_in[15];
    const float* ca_Wk = (const float*)d_in[16];
    const float* ca_Wv = (const float*)d_in[17];
    const float* ca_Wq = (const float*)d_in[18];
    const float* ca_Wf = (const float*)d_in[19];
    const float* ca_bf = (const float*)d_in[20];
    const float* ca_g  = (const float*)d_in[21];
    const float* ca_b  = (const float*)d_in[22];

    Bufs Z;
    cudaGetSymbolAddress((void**)&Z.e,   g_e);
    cudaGetSymbolAddress((void**)&Z.er,  g_er);
    cudaGetSymbolAddress((void**)&Z.e1,  g_e1);
    cudaGetSymbolAddress((void**)&Z.e2,  g_e2);
    cudaGetSymbolAddress((void**)&Z.e3,  g_e3);
    cudaGetSymbolAddress((void**)&Z.qb,  g_qb);
    cudaGetSymbolAddress((void**)&Z.qbr, g_qbr);
    cudaGetSymbolAddress((void**)&Z.kbr, g_kbr);
    cudaGetSymbolAddress((void**)&Z.R,   g_R);
    cudaGetSymbolAddress((void**)&Z.T,   g_T);
    cudaGetSymbolAddress((void**)&Z.QKV, g_QKV);
    cudaGetSymbolAddress((void**)&Z.Vt,  g_Vt);
    cudaGetSymbolAddress((void**)&Z.R4,  g_R4);
    cudaGetSymbolAddress((void**)&Z.S,   g_S);
    cudaGetSymbolAddress((void**)&Z.S16, g_S16);
    cudaGetSymbolAddress((void**)&Z.Wc,  g_Wc);
    cudaGetSymbolAddress((void**)&Z.Wf,  g_Wf);

    const long WW  = (long)HD * HD;
    const long WCL = (long)QW * 512;     // fused weight per layer (halfs)
    const long WFC = (long)512 * 512;    // one Wf chunk (halfs)

    // ---- weight prep ----
    {
        int n = 512 * 512, nb = (n + 255) / 256;
        for (int i = 0; i < 2; i++) {
            pack_qkv_t<<<nb, 256>>>(sc_Wk + i * WW, sc_Wv + i * WW, sc_Wq + i * WW,
                                    Z.Wc + i * WCL);
            pack_qkv_t<<<nb, 256>>>(ca_Wk + i * WW, ca_Wv + i * WW, ca_Wq + i * WW,
                                    Z.Wc + (2 + i) * WCL);
            wf_t_kernel<<<nb, 256>>>(sc_Wf + i * 2 * WW,
                                     Z.Wf + (2 * i) * WFC, Z.Wf + (2 * i + 1) * WFC);
            wf_t_kernel<<<nb, 256>>>(ca_Wf + i * 2 * WW,
                                     Z.Wf + (4 + 2 * i) * WFC, Z.Wf + (5 + 2 * i) * WFC);
        }
    }

    const int nthr = 256, nblk = (RR * HD + nthr - 1) / nthr;

    // ---- input projections ----
    proj_in_kernel<<<nblk, nthr>>>(context_x, context_y, in_W, in_b, Z.e, Z.er, 0);
    proj_in_kernel<<<nblk, nthr>>>(context_x, context_y, in_W, in_b, nullptr, Z.e1, 1);
    proj_in_kernel<<<nblk, nthr>>>(context_x, context_y, in_W, in_b, nullptr, Z.e2, 2);
    proj_in_kernel<<<nblk, nthr>>>(context_x, context_y, in_W, in_b, nullptr, Z.e3, 3);

    // ---- encoder ----
    for (int i = 0; i < 2; i++)
        sc_attn(Z, Z.e, Z.er, Z.er, true,
                Z.Wc + i * WCL, Z.Wf + (2 * i) * WFC, Z.Wf + (2 * i + 1) * WFC,
                sc_bf + i * HD, sc_g + i * HD, sc_b + i * HD);

    const __half* xs2[3] = { Z.e1, Z.e2, Z.e3 };
    for (int s = 0; s < 3; s++)
        for (int i = 0; i < 2; i++)
            sc_attn(Z, Z.e, Z.er, xs2[s], false,
                    Z.Wc + i * WCL, Z.Wf + (2 * i) * WFC, Z.Wf + (2 * i + 1) * WFC,
                    sc_bf + i * HD, sc_g + i * HD, sc_b + i * HD);

    // ---- decoder inputs ----
    proj1_kernel<<<nblk, nthr>>>(target_x,  tx_W, tx_b, Z.qb, Z.qbr);
    proj1_kernel<<<nblk, nthr>>>(context_x, cx_W, cx_b, nullptr, Z.kbr);

    // ---- decoder ----
    for (int i = 0; i < 2; i++)
        cross_attn(Z, Z.qb, Z.qbr, Z.kbr, Z.er,
                   Z.Wc + (2 + i) * WCL, Z.Wf + (4 + 2 * i) * WFC, Z.Wf + (5 + 2 * i) * WFC,
                   ca_bf + i * HD, ca_g + i * HD, ca_b + i * HD);

    cudaMemcpyAsync(d_out, Z.qb, (size_t)RR * HD * sizeof(float),
                    cudaMemcpyDeviceToDevice);
}

// round 10
// speedup vs baseline: 10.0441x; 1.1917x over previous
#include <cuda_runtime.h>
#include <cuda_fp16.h>
#include <math.h>
#include <stdint.h>

// ---------------------------------------------------------------------------
// MultidomainEncoder: B=4, N=M=1024, H=512.
// Round 9: fp16 mma.sync GEMM; SDPA prob-fold (4 AV -> 1 K=2048 AV);
// [x|R] fused state buffer -> single K=1024 Wf GEMM; batched QKV launches.
// ---------------------------------------------------------------------------

#define RR   4096          // B*N == B*M rows
#define HD   512           // model dim
#define QW   1536          // fused QKV row width

__device__ float  g_e   [RR * HD];                    // exact encoder state
__device__ __half g_enc [4 * (size_t)RR * 1024];      // [XRe | e1 | e2 | e3] (ld 1024)
__device__ __half g_xrq [(size_t)RR * 1024];          // decoder [qbr | R] (ld 1024)
__device__ float  g_qb  [RR * HD];                    // exact decoder state
__device__ float  g_T   [RR * HD];
__device__ __half g_QKV [2 * (size_t)RR * QW];        // two fused QKV buffers
__device__ __half g_Vt  [(size_t)8 * 1024 * 1024];    // transposed V
__device__ float  g_S   [(size_t)32 * 1024 * 1024];   // pre-softmax scores (fp32)
__device__ __half g_S16 [(size_t)8 * 1024 * 2048];    // folded probs (fp16)
__device__ __half g_Wc  [4 * (size_t)QW * 512];       // transposed fused QKV weights
__device__ __half g_Wf  [4 * (size_t)512 * 1024];     // transposed full Wf per layer

static const long QBUF  = (long)RR * QW;              // QKV buffer stride (halfs)
static const long SSEGf = (long)8 * 1024 * 1024;      // S segment per combo (floats)
static const long ENCR  = (long)RR * 1024;            // one g_enc region (halfs)

// ---------------------------------------------------------------------------
// helpers
// ---------------------------------------------------------------------------
__device__ __forceinline__ void mma_f16(float c[4], const uint32_t a[4], const uint32_t b[2]) {
    asm volatile(
        "mma.sync.aligned.m16n8k16.row.col.f32.f16.f16.f32 "
        "{%0,%1,%2,%3}, {%4,%5,%6,%7}, {%8,%9}, {%0,%1,%2,%3};"
        : "+f"(c[0]), "+f"(c[1]), "+f"(c[2]), "+f"(c[3])
        : "r"(a[0]), "r"(a[1]), "r"(a[2]), "r"(a[3]), "r"(b[0]), "r"(b[1]));
}

__device__ __forceinline__ void cp16(uint32_t* dst, const void* src) {
    uint32_t d = (uint32_t)__cvta_generic_to_shared(dst);
    asm volatile("cp.async.cg.shared.global [%0], [%1], 16;" :: "r"(d), "l"(src));
}
#define CP_COMMIT() asm volatile("cp.async.commit_group;" ::: "memory")
#define CP_WAIT1()  asm volatile("cp.async.wait_group 1;"  ::: "memory")
#define CP_WAIT0()  asm volatile("cp.async.wait_group 0;"  ::: "memory")

struct Offs { long a[4]; long b[4]; long c[4]; };

// ---------------------------------------------------------------------------
// fp16 GEMM:  C[m,n] = alpha * sum_k A[m,k] * B[n,k]  [+bias] [+C]
// A: [M,K] row-major fp16 (lda); B: [N,K] row-major fp16 (ldb).
// C: fp32 (outHalf=0) or fp16 (outHalf=1).
// Tile 128x128x32, 256 threads (8 warps, warp tile 64x32), cp.async 2-stage.
// ---------------------------------------------------------------------------
#define WPR 20   // words per smem row (16 data + 4 pad)

__global__ void __launch_bounds__(256)
gemm_h(const __half* __restrict__ A, const __half* __restrict__ B,
       void* __restrict__ Cv, const float* __restrict__ bias,
       int K, int lda, int ldb, int ldc,
       long sAb, long sAh, long sBb, long sBh, long sCb, long sCh,
       int nh, int nzc, Offs off, float alpha, int accumulate, int outHalf)
{
    __shared__ uint32_t sA[2][128 * WPR];
    __shared__ uint32_t sB[2][128 * WPR];

    int z   = blockIdx.z;
    int cmb = z / nzc;
    int inn = z - cmb * nzc;
    int bb  = inn / nh;
    int hh  = inn - bb * nh;
    A += off.a[cmb] + (long)bb * sAb + (long)hh * sAh;
    B += off.b[cmb] + (long)bb * sBb + (long)hh * sBh;
    long coff = off.c[cmb] + (long)bb * sCb + (long)hh * sCh;

    const int row0 = blockIdx.y * 128;
    const int col0 = blockIdx.x * 128;
    const int tid  = threadIdx.x;
    const int wid  = tid >> 5;
    const int lane = tid & 31;
    const int wM0 = (wid & 1) * 64;
    const int wN0 = (wid >> 1) * 32;
    const int gid = lane >> 2;
    const int tig = lane & 3;

    float acc[4][4][4] = {};

    const int lrow = tid >> 1;
    const int lsel = tid & 1;

    auto loadTile = [&](int t, int s) {
        const __half* ga = A + (long)(row0 + lrow) * lda + t * 32 + lsel * 16;
        const __half* gb = B + (long)(col0 + lrow) * ldb + t * 32 + lsel * 16;
        uint32_t* sa = &sA[s][lrow * WPR + lsel * 8];
        uint32_t* sb = &sB[s][lrow * WPR + lsel * 8];
        cp16(sa, ga); cp16(sa + 4, ga + 8);
        cp16(sb, gb); cp16(sb + 4, gb + 8);
    };

    const int nT = K / 32;
    loadTile(0, 0);
    CP_COMMIT();

    for (int t = 0; t < nT; t++) {
        int s = t & 1;
        if (t + 1 < nT) {
            loadTile(t + 1, s ^ 1);
            CP_COMMIT();
            CP_WAIT1();
        } else {
            CP_WAIT0();
        }
        __syncthreads();

        const uint32_t* Ap = sA[s];
        const uint32_t* Bp = sB[s];
#pragma unroll
        for (int ko = 0; ko < 16; ko += 8) {
            uint32_t af[4][4], bfr[4][2];
#pragma unroll
            for (int mt = 0; mt < 4; mt++) {
                int m = wM0 + mt * 16 + gid;
                af[mt][0] = Ap[m * WPR + ko + tig];
                af[mt][1] = Ap[(m + 8) * WPR + ko + tig];
                af[mt][2] = Ap[m * WPR + ko + 4 + tig];
                af[mt][3] = Ap[(m + 8) * WPR + ko + 4 + tig];
            }
#pragma unroll
            for (int nt = 0; nt < 4; nt++) {
                int n = wN0 + nt * 8 + gid;
                bfr[nt][0] = Bp[n * WPR + ko + tig];
                bfr[nt][1] = Bp[n * WPR + ko + 4 + tig];
            }
#pragma unroll
            for (int mt = 0; mt < 4; mt++)
#pragma unroll
                for (int nt = 0; nt < 4; nt++)
                    mma_f16(acc[mt][nt], af[mt], bfr[nt]);
        }
        __syncthreads();
    }

    if (!outHalf) {
        float* C = (float*)Cv + coff;
#pragma unroll
        for (int mt = 0; mt < 4; mt++) {
            int r = row0 + wM0 + mt * 16 + gid;
#pragma unroll
            for (int nt = 0; nt < 4; nt++) {
                int c = col0 + wN0 + nt * 8 + tig * 2;
                float b0 = 0.f, b1 = 0.f;
                if (bias) { b0 = bias[c]; b1 = bias[c + 1]; }
                float2 v0, v1;
                v0.x = alpha * acc[mt][nt][0] + b0;
                v0.y = alpha * acc[mt][nt][1] + b1;
                v1.x = alpha * acc[mt][nt][2] + b0;
                v1.y = alpha * acc[mt][nt][3] + b1;
                float* p0 = &C[(long)r * ldc + c];
                float* p1 = &C[(long)(r + 8) * ldc + c];
                if (accumulate) {
                    float2 o0 = *(const float2*)p0, o1 = *(const float2*)p1;
                    v0.x += o0.x; v0.y += o0.y; v1.x += o1.x; v1.y += o1.y;
                }
                *(float2*)p0 = v0;
                *(float2*)p1 = v1;
            }
        }
    } else {
        __half* C = (__half*)Cv + coff;
#pragma unroll
        for (int mt = 0; mt < 4; mt++) {
            int r = row0 + wM0 + mt * 16 + gid;
#pragma unroll
            for (int nt = 0; nt < 4; nt++) {
                int c = col0 + wN0 + nt * 8 + tig * 2;
                __half2 h0 = __floats2half2_rn(alpha * acc[mt][nt][0], alpha * acc[mt][nt][1]);
                __half2 h1 = __floats2half2_rn(alpha * acc[mt][nt][2], alpha * acc[mt][nt][3]);
                *(__half2*)&C[(long)r * ldc + c]       = h0;
                *(__half2*)&C[(long)(r + 8) * ldc + c] = h1;
            }
        }
    }
}

// ---------------------------------------------------------------------------
// Single softmax (L=1024): S fp32 in (contiguous rows), S16 fp16 out (ld 1024).
// ---------------------------------------------------------------------------
__global__ void softmax1(const float* __restrict__ S, __half* __restrict__ S16)
{
    const float4* p = (const float4*)(S + (long)blockIdx.x * 1024);
    __half2* o = (__half2*)(S16 + (long)blockIdx.x * 1024);
    int tid = threadIdx.x, lane = tid & 31, wid = tid >> 5;
    __shared__ float red[16];

    float4 v = p[tid];
    float m = fmaxf(fmaxf(v.x, v.y), fmaxf(v.z, v.w));
#pragma unroll
    for (int t = 16; t > 0; t >>= 1) m = fmaxf(m, __shfl_xor_sync(0xffffffffu, m, t));
    if (lane == 0) red[wid] = m;
    __syncthreads();
    m = red[0];
#pragma unroll
    for (int i = 1; i < 8; i++) m = fmaxf(m, red[i]);

    v.x = __expf(v.x - m); v.y = __expf(v.y - m);
    v.z = __expf(v.z - m); v.w = __expf(v.w - m);
    float sum = v.x + v.y + v.z + v.w;
#pragma unroll
    for (int t = 16; t > 0; t >>= 1) sum += __shfl_xor_sync(0xffffffffu, sum, t);
    if (lane == 0) red[8 + wid] = sum;
    __syncthreads();
    sum = red[8];
#pragma unroll
    for (int i = 1; i < 8; i++) sum += red[8 + i];
    float inv = 1.f / sum;

    o[2 * tid]     = __floats2half2_rn(v.x * inv, v.y * inv);
    o[2 * tid + 1] = __floats2half2_rn(v.z * inv, v.w * inv);
}

// ---------------------------------------------------------------------------
// Paired softmax + fold (cross layers):
//   g=0: P_s = softmax(seg0 row) + softmax(seg2 row) -> S16[row][0:1024]
//   g=1: P_c = softmax(seg1 row) + softmax(seg3 row) -> S16[row][1024:2048]
// blockIdx.x = g*8192 + bh*1024 + row
// ---------------------------------------------------------------------------
__global__ void softmax_pair(const float* __restrict__ S, __half* __restrict__ S16)
{
    int bid = blockIdx.x;
    int g   = bid >> 13;
    int rem = bid & 8191;                     // bh*1024 + row
    long roff = (long)rem << 10;
    const float4* pa = (const float4*)(S + (long)g * SSEGf + roff);
    const float4* pb = (const float4*)(S + (long)(g + 2) * SSEGf + roff);
    __half2* out = (__half2*)(S16 + ((long)rem << 11) + ((long)g << 10));
    int tid = threadIdx.x, lane = tid & 31, wid = tid >> 5;
    __shared__ float red[32];

    float4 va = pa[tid], vb = pb[tid];
    float ma = fmaxf(fmaxf(va.x, va.y), fmaxf(va.z, va.w));
    float mb = fmaxf(fmaxf(vb.x, vb.y), fmaxf(vb.z, vb.w));
#pragma unroll
    for (int t = 16; t > 0; t >>= 1) {
        ma = fmaxf(ma, __shfl_xor_sync(0xffffffffu, ma, t));
        mb = fmaxf(mb, __shfl_xor_sync(0xffffffffu, mb, t));
    }
    if (lane == 0) { red[wid] = ma; red[8 + wid] = mb; }
    __syncthreads();
    ma = red[0]; mb = red[8];
#pragma unroll
    for (int i = 1; i < 8; i++) { ma = fmaxf(ma, red[i]); mb = fmaxf(mb, red[8 + i]); }

    va.x = __expf(va.x - ma); va.y = __expf(va.y - ma);
    va.z = __expf(va.z - ma); va.w = __expf(va.w - ma);
    vb.x = __expf(vb.x - mb); vb.y = __expf(vb.y - mb);
    vb.z = __expf(vb.z - mb); vb.w = __expf(vb.w - mb);
    float sa = va.x + va.y + va.z + va.w;
    float sb = vb.x + vb.y + vb.z + vb.w;
#pragma unroll
    for (int t = 16; t > 0; t >>= 1) {
        sa += __shfl_xor_sync(0xffffffffu, sa, t);
        sb += __shfl_xor_sync(0xffffffffu, sb, t);
    }
    if (lane == 0) { red[16 + wid] = sa; red[24 + wid] = sb; }
    __syncthreads();
    sa = red[16]; sb = red[24];
#pragma unroll
    for (int i = 1; i < 8; i++) { sa += red[16 + i]; sb += red[24 + i]; }
    float ia = 1.f / sa, ib = 1.f / sb;

    out[2 * tid]     = __floats2half2_rn(va.x * ia + vb.x * ib, va.y * ia + vb.y * ib);
    out[2 * tid + 1] = __floats2half2_rn(va.z * ia + vb.z * ib, va.w * ia + vb.w * ib);
}

// ---------------------------------------------------------------------------
// transpose V head-slices: src [4*1024 rows, ldsrc] cols [512 + h*d, +d)
//  -> dst[z][n][dstLd] at column offset dstOff  (z = b*hn + h)
// ---------------------------------------------------------------------------
__global__ void transpose_v(const __half* __restrict__ src, __half* __restrict__ dst,
                            int ldsrc, int d, int hn, int dstLd, int dstOff)
{
    __shared__ __half t[32][34];
    int z = blockIdx.z;
    int b = z / hn, h = z - b * hn;
    int m0 = blockIdx.x * 32, c0 = blockIdx.y * 32;
    const __half* s = src + (long)(b * 1024) * ldsrc + 512 + h * d;
    int tx = threadIdx.x, ty = threadIdx.y;
#pragma unroll
    for (int i = 0; i < 4; i++)
        t[ty + i * 8][tx] = s[(long)(m0 + ty + i * 8) * ldsrc + c0 + tx];
    __syncthreads();
    __half* o = dst + (long)z * d * dstLd + dstOff;
#pragma unroll
    for (int i = 0; i < 4; i++)
        o[(long)(c0 + ty + i * 8) * dstLd + m0 + tx] = t[tx][ty + i * 8];
}

// ---------------------------------------------------------------------------
// out = LayerNorm(tmp + res) * g + b ; writes exact fp32 + fp16 into state
// buffer (ld 1024, cols 0..511).
// ---------------------------------------------------------------------------
__global__ void add_ln_kernel(const float* __restrict__ tmp, const float* __restrict__ res,
                              const float* __restrict__ g, const float* __restrict__ b,
                              float* __restrict__ out, __half* __restrict__ outh)
{
    long row = blockIdx.x;
    const float* t = tmp + row * (long)HD;
    const float* r = res + row * (long)HD;
    float* o = out + row * (long)HD;
    __half* oh = outh + row * 1024;
    __shared__ float red[256];
    int tid = threadIdx.x;

    float v0 = t[tid]       + r[tid];
    float v1 = t[tid + 256] + r[tid + 256];
    red[tid] = v0 + v1; __syncthreads();
    for (int s = 128; s > 0; s >>= 1) { if (tid < s) red[tid] += red[tid + s]; __syncthreads(); }
    float mean = red[0] * (1.f / HD);
    __syncthreads();
    float d0 = v0 - mean, d1 = v1 - mean;
    red[tid] = d0 * d0 + d1 * d1; __syncthreads();
    for (int s = 128; s > 0; s >>= 1) { if (tid < s) red[tid] += red[tid + s]; __syncthreads(); }
    float rstd = rsqrtf(red[0] * (1.f / HD) + 1e-5f);
    float w0 = d0 * rstd * g[tid]       + b[tid];
    float w1 = d1 * rstd * g[tid + 256] + b[tid + 256];
    o[tid]       = w0;
    o[tid + 256] = w1;
    oh[tid]       = __float2half_rn(w0);
    oh[tid + 256] = __float2half_rn(w1);
}

// ---------------------------------------------------------------------------
// Input projections (fp16 out with ld; optional fp32 exact copy)
// ---------------------------------------------------------------------------
__global__ void proj_in_kernel(const float* __restrict__ cx, const float* __restrict__ cy,
                               const float* __restrict__ W, const float* __restrict__ bias,
                               float* __restrict__ out, __half* __restrict__ outh,
                               int ldo, int j)
{
    int idx = blockIdx.x * blockDim.x + threadIdx.x;
    if (idx >= RR * HD) return;
    int r = idx >> 9;
    int h = idx & (HD - 1);
    float x0 = cx[r];
    float y0 = cy[r * 8 + j * 2];
    float y1 = cy[r * 8 + j * 2 + 1];
    float v = x0 * W[h] + y0 * W[HD + h] + y1 * W[2 * HD + h] + bias[h];
    if (out) out[idx] = v;
    outh[(long)r * ldo + h] = __float2half_rn(v);
}

__global__ void proj1_kernel(const float* __restrict__ x, const float* __restrict__ W,
                             const float* __restrict__ bias,
                             float* __restrict__ out, __half* __restrict__ outh, int ldo)
{
    int idx = blockIdx.x * blockDim.x + threadIdx.x;
    if (idx >= RR * HD) return;
    int r = idx >> 9;
    int h = idx & (HD - 1);
    float v = x[r] * W[h] + bias[h];
    if (out) out[idx] = v;
    outh[(long)r * ldo + h] = __float2half_rn(v);
}

// ---------------------------------------------------------------------------
// Weight prep (tiled transposes, coalesced both sides)
// wprep_qkv: z = L*3+m; L in {sc0,sc1,ca0,ca1}, m in {K,V,Q}.
//   dst[n][k] (ld 512) at Wc + L*QW*512 + m*512*512
// ---------------------------------------------------------------------------
__global__ void wprep_qkv(const float* __restrict__ sWk, const float* __restrict__ sWv,
                          const float* __restrict__ sWq, const float* __restrict__ cWk,
                          const float* __restrict__ cWv, const float* __restrict__ cWq,
                          __half* __restrict__ Wc)
{
    __shared__ float t[32][33];
    int z = blockIdx.z;
    int L = z / 3, m = z - L * 3;
    const float* base;
    if (L < 2) base = (m == 0 ? sWk : m == 1 ? sWv : sWq) + (long)L * 512 * 512;
    else       base = (m == 0 ? cWk : m == 1 ? cWv : cWq) + (long)(L - 2) * 512 * 512;
    __half* dst = Wc + (long)L * QW * 512 + (long)m * 512 * 512;
    int n0 = blockIdx.x * 32, k0 = blockIdx.y * 32;
    int tx = threadIdx.x, ty = threadIdx.y;
#pragma unroll
    for (int i = 0; i < 4; i++)
        t[ty + i * 8][tx] = base[(long)(k0 + ty + i * 8) * 512 + n0 + tx];
    __syncthreads();
#pragma unroll
    for (int i = 0; i < 4; i++)
        dst[(long)(n0 + ty + i * 8) * 512 + k0 + tx] = __float2half_rn(t[tx][ty + i * 8]);
}

// wprep_wf: z in {sc0,sc1,ca0,ca1}; src [1024 x 512] -> dst [512][1024]
__global__ void wprep_wf(const float* __restrict__ sWf, const float* __restrict__ cWf,
                         __half* __restrict__ Wf)
{
    __shared__ float t[32][33];
    int z = blockIdx.z;
    const float* src = (z < 2 ? sWf : cWf) + (long)(z & 1) * 1024 * 512;
    __half* dst = Wf + (long)z * 512 * 1024;
    int k0 = blockIdx.x * 32, n0 = blockIdx.y * 32;
    int tx = threadIdx.x, ty = threadIdx.y;
#pragma unroll
    for (int i = 0; i < 4; i++)
        t[ty + i * 8][tx] = src[(long)(k0 + ty + i * 8) * 512 + n0 + tx];
    __syncthreads();
#pragma unroll
    for (int i = 0; i < 4; i++)
        dst[(long)(n0 + ty + i * 8) * 1024 + k0 + tx] = __float2half_rn(t[tx][ty + i * 8]);
}

// ---------------------------------------------------------------------------
// Host orchestration
// ---------------------------------------------------------------------------
static void gemmH(const __half* A, const __half* B, void* C, const float* bias,
                  int M, int N, int K, int lda, int ldb, int ldc,
                  long sAb, long sAh, long sBb, long sBh, long sCb, long sCh,
                  int nb, int nh, int ncomb, const Offs& off,
                  float alpha, int acc, int outHalf)
{
    dim3 grid(N / 128, M / 128, ncomb * nb * nh);
    gemm_h<<<grid, 256>>>(A, B, C, bias, K, lda, ldb, ldc,
                          sAb, sAh, sBb, sBh, sCb, sCh,
                          nh, nb * nh, off, alpha, acc, outHalf);
}

struct Bufs {
    float *e, *qb, *T, *S;
    __half *enc, *xrq, *QKV, *Vt, *S16, *Wc, *Wf;
};

// Encoder self/cross layer. State: g_e (fp32) + enc cols 0..511 (fp16).
static void sc_attn(Bufs& Z, bool same, long x2off,
                    const __half* Wct, const __half* WfT,
                    const float* bf, const float* gg, const float* bb)
{
    const float scale = rsqrtf(256.f);
    Offs z0 = {};

    // fused QKV (batched over {state, x2} when cross)
    {
        Offs oP = {};
        int nc = 1;
        if (!same) { oP.a[1] = x2off; oP.c[1] = QBUF; nc = 2; }
        gemmH(Z.enc, Wct, Z.QKV, nullptr, RR, QW, HD, 1024, HD, QW,
              0,0,0,0,0,0, 1,1, nc, oP, 1.f, 0, 1);
    }

    // transpose V into Vt
    if (same) {
        transpose_v<<<dim3(32, 8, 8), dim3(32, 8)>>>(Z.QKV, Z.Vt, QW, 256, 2, 1024, 0);
    } else {
        transpose_v<<<dim3(32, 8, 8), dim3(32, 8)>>>(Z.QKV, Z.Vt, QW, 256, 2, 2048, 0);
        transpose_v<<<dim3(32, 8, 8), dim3(32, 8)>>>(Z.QKV + QBUF, Z.Vt, QW, 256, 2, 2048, 1024);
    }

    // QK scores -> S (fp32)
    {
        Offs oQK = {};
        int nc = 1;
        if (same) {
            oQK.a[0] = 1024;
        } else {
            const long selQ[4] = {0, 1, 1, 0};
            const long selK[4] = {0, 1, 0, 1};
            for (int c = 0; c < 4; c++) {
                oQK.a[c] = selQ[c] * QBUF + 1024;
                oQK.b[c] = selK[c] * QBUF;
                oQK.c[c] = c * SSEGf;
            }
            nc = 4;
        }
        gemmH(Z.QKV, Z.QKV, Z.S, nullptr, 1024, 1024, 256, QW, QW, 1024,
              (long)1024 * QW, 256, (long)1024 * QW, 256,
              (long)2 * 1024 * 1024, (long)1024 * 1024,
              4, 2, nc, oQK, scale, 0, 0);
    }

    if (same) {
        softmax1<<<8 * 1024, 256>>>(Z.S, Z.S16);
        // AV -> enc cols 512..1023, alpha = 4 (four identical combos)
        gemmH(Z.S16, Z.Vt, Z.enc + 512, nullptr, 1024, 256, 1024, 1024, 1024, 1024,
              (long)2 * 1024 * 1024, (long)1024 * 1024,
              (long)2 * 256 * 1024, (long)256 * 1024,
              (long)1024 * 1024, 256,
              4, 2, 1, z0, 4.f, 0, 1);
    } else {
        softmax_pair<<<2 * 8 * 1024, 256>>>(Z.S, Z.S16);
        // folded AV: K=2048 ([P_s|P_c] @ [Vs;Vc])
        gemmH(Z.S16, Z.Vt, Z.enc + 512, nullptr, 1024, 256, 2048, 2048, 2048, 1024,
              (long)2 * 1024 * 2048, (long)1024 * 2048,
              (long)2 * 256 * 2048, (long)256 * 2048,
              (long)1024 * 1024, 256,
              4, 2, 1, z0, 1.f, 0, 1);
    }

    // T = [x | R] @ WfT + bf   (single K=1024 GEMM)
    gemmH(Z.enc, WfT, Z.T, bf, RR, HD, 1024, 1024, 1024, HD,
          0,0,0,0,0,0, 1,1,1, z0, 1.f, 0, 0);

    add_ln_kernel<<<RR, 256>>>(Z.T, Z.e, gg, bb, Z.e, Z.enc);
}

// Decoder cross-attn layer (h=4, d=128). State: g_qb + xrq cols 0..511.
static void cross_attn(Bufs& Z, const __half* Wct, const __half* WfT,
                       const float* bf, const float* gg, const float* bb)
{
    const float scale = rsqrtf(128.f);
    Offs z0 = {};

    // K proj (from kbr in enc region 1) + V proj (from encoder state) batched
    {
        Offs oKV = {};
        oKV.a[0] = ENCR; oKV.b[0] = 0;              oKV.c[0] = 0;
        oKV.a[1] = 0;    oKV.b[1] = (long)512 * 512; oKV.c[1] = 512;
        gemmH(Z.enc, Wct, Z.QKV, nullptr, RR, 512, HD, 1024, HD, QW,
              0,0,0,0,0,0, 1,1,2, oKV, 1.f, 0, 1);
    }
    // Q proj from decoder state
    gemmH(Z.xrq, Wct + (long)1024 * 512, Z.QKV + 1024, nullptr, RR, 512, HD, 1024, HD, QW,
          0,0,0,0,0,0, 1,1,1, z0, 1.f, 0, 1);

    transpose_v<<<dim3(32, 4, 16), dim3(32, 8)>>>(Z.QKV, Z.Vt, QW, 128, 4, 1024, 0);

    Offs oQK = {}; oQK.a[0] = 1024;
    gemmH(Z.QKV, Z.QKV, Z.S, nullptr, 1024, 1024, 128, QW, QW, 1024,
          (long)1024 * QW, 128, (long)1024 * QW, 128,
          (long)4 * 1024 * 1024, (long)1024 * 1024,
          4, 4, 1, oQK, scale, 0, 0);

    softmax1<<<16 * 1024, 256>>>(Z.S, Z.S16);

    gemmH(Z.S16, Z.Vt, Z.xrq + 512, nullptr, 1024, 128, 1024, 1024, 1024, 1024,
          (long)4 * 1024 * 1024, (long)1024 * 1024,
          (long)4 * 128 * 1024, (long)128 * 1024,
          (long)1024 * 1024, 128,
          4, 4, 1, z0, 1.f, 0, 1);

    gemmH(Z.xrq, WfT, Z.T, bf, RR, HD, 1024, 1024, 1024, HD,
          0,0,0,0,0,0, 1,1,1, z0, 1.f, 0, 0);

    add_ln_kernel<<<RR, 256>>>(Z.T, Z.qb, gg, bb, Z.qb, Z.xrq);
}

extern "C" void kernel_launch(void* const* d_in, const int* in_sizes, int n_in,
                              void* d_out, int out_size)
{
    const float* context_x = (const float*)d_in[0];
    const float* context_y = (const float*)d_in[1];
    const float* target_x  = (const float*)d_in[2];
    const float* in_W = (const float*)d_in[3];
    const float* in_b = (const float*)d_in[4];
    const float* cx_W = (const float*)d_in[5];
    const float* cx_b = (const float*)d_in[6];
    const float* tx_W = (const float*)d_in[7];
    const float* tx_b = (const float*)d_in[8];
    const float* sc_Wk = (const float*)d_in[9];
    const float* sc_Wv = (const float*)d_in[10];
    const float* sc_Wq = (const float*)d_in[11];
    const float* sc_Wf = (const float*)d_in[12];
    const float* sc_bf = (const float*)d_in[13];
    const float* sc_g  = (const float*)d_in[14];
    const float* sc_b  = (const float*)d_in[15];
    const float* ca_Wk = (const float*)d_in[16];
    const float* ca_Wv = (const float*)d_in[17];
    const float* ca_Wq = (const float*)d_in[18];
    const float* ca_Wf = (const float*)d_in[19];
    const float* ca_bf = (const float*)d_in[20];
    const float* ca_g  = (const float*)d_in[21];
    const float* ca_b  = (const float*)d_in[22];

    Bufs Z;
    cudaGetSymbolAddress((void**)&Z.e,   g_e);
    cudaGetSymbolAddress((void**)&Z.qb,  g_qb);
    cudaGetSymbolAddress((void**)&Z.T,   g_T);
    cudaGetSymbolAddress((void**)&Z.S,   g_S);
    cudaGetSymbolAddress((void**)&Z.enc, g_enc);
    cudaGetSymbolAddress((void**)&Z.xrq, g_xrq);
    cudaGetSymbolAddress((void**)&Z.QKV, g_QKV);
    cudaGetSymbolAddress((void**)&Z.Vt,  g_Vt);
    cudaGetSymbolAddress((void**)&Z.S16, g_S16);
    cudaGetSymbolAddress((void**)&Z.Wc,  g_Wc);
    cudaGetSymbolAddress((void**)&Z.Wf,  g_Wf);

    const long WCL = (long)QW * 512;     // fused QKV weight per layer (halfs)
    const long WFL = (long)512 * 1024;   // Wf per layer (halfs)

    // ---- weight prep (2 launches, tiled transposes) ----
    wprep_qkv<<<dim3(16, 16, 12), dim3(32, 8)>>>(sc_Wk, sc_Wv, sc_Wq,
                                                 ca_Wk, ca_Wv, ca_Wq, Z.Wc);
    wprep_wf<<<dim3(32, 16, 4), dim3(32, 8)>>>(sc_Wf, ca_Wf, Z.Wf);

    const int nthr = 256, nblk = (RR * HD + nthr - 1) / nthr;

    // ---- input projections ----
    proj_in_kernel<<<nblk, nthr>>>(context_x, context_y, in_W, in_b, Z.e, Z.enc, 1024, 0);
    proj_in_kernel<<<nblk, nthr>>>(context_x, context_y, in_W, in_b, nullptr, Z.enc + ENCR,     1024, 1);
    proj_in_kernel<<<nblk, nthr>>>(context_x, context_y, in_W, in_b, nullptr, Z.enc + 2 * ENCR, 1024, 2);
    proj_in_kernel<<<nblk, nthr>>>(context_x, context_y, in_W, in_b, nullptr, Z.enc + 3 * ENCR, 1024, 3);

    // ---- encoder ----
    for (int i = 0; i < 2; i++)
        sc_attn(Z, true, 0, Z.Wc + i * WCL, Z.Wf + i * WFL,
                sc_bf + i * HD, sc_g + i * HD, sc_b + i * HD);

    for (int s = 0; s < 3; s++)
        for (int i = 0; i < 2; i++)
            sc_attn(Z, false, (long)(s + 1) * ENCR, Z.Wc + i * WCL, Z.Wf + i * WFL,
                    sc_bf + i * HD, sc_g + i * HD, sc_b + i * HD);

    // ---- decoder inputs ----
    proj1_kernel<<<nblk, nthr>>>(target_x,  tx_W, tx_b, Z.qb, Z.xrq, 1024);
    proj1_kernel<<<nblk, nthr>>>(context_x, cx_W, cx_b, nullptr, Z.enc + ENCR, 1024);  // kbr -> e1 region

    // ---- decoder ----
    for (int i = 0; i < 2; i++)
        cross_attn(Z, Z.Wc + (2 + i) * WCL, Z.Wf + (2 + i) * WFL,
                   ca_bf + i * HD, ca_g + i * HD, ca_b + i * HD);

    cudaMemcpyAsync(d_out, Z.qb, (size_t)RR * HD * sizeof(float),
                    cudaMemcpyDeviceToDevice);
}

// round 13
// speedup vs baseline: 10.6545x; 1.0608x over previous
#include <cuda_runtime.h>
#include <cuda_fp16.h>
#include <math.h>
#include <stdint.h>

// ---------------------------------------------------------------------------
// MultidomainEncoder: B=4, N=M=1024, H=512.
// Round 10: exploit rank-4 domain inputs — x2 QKV / first-layer QKV /
// decoder K,Q projections become K=4 skinny products (T = M_aug @ W computed
// once in fp32). fp16 mma.sync GEMM, prob-fold AV, fused [x|R] Wf unchanged.
// ---------------------------------------------------------------------------

#define RR   4096          // B*N == B*M rows
#define HD   512           // model dim
#define QW   1536          // fused QKV row width

__device__ float  g_e   [RR * HD];                    // exact encoder state
__device__ __half g_enc [3 * (size_t)RR * 1024];      // region0: [x|R]; region2: decoder [q|R]
__device__ float  g_qb  [RR * HD];                    // exact decoder state
__device__ float  g_T   [RR * HD];
__device__ __half g_QKV [2 * (size_t)RR * QW];        // QKV buffers (state / x2)
__device__ __half g_Vt  [(size_t)8 * 1024 * 1024];    // transposed V
__device__ float  g_S   [(size_t)32 * 1024 * 1024];   // pre-softmax scores (fp32)
__device__ __half g_S16 [(size_t)8 * 1024 * 2048];    // folded probs (fp16)
__device__ __half g_Wc  [4 * (size_t)QW * 512];       // transposed fused QKV weights
__device__ __half g_Wf  [4 * (size_t)512 * 1024];     // transposed full Wf per layer
__device__ float  g_F   [4 * (size_t)RR * 4];         // encoder rank-4 factors per stream
__device__ float  g_Fdk [RR * 4];                     // decoder K factor [cx,1,0,0]
__device__ float  g_Fdq [RR * 4];                     // decoder Q factor [tx,1,0,0]
__device__ float  g_Tenc[2 * 4 * QW];                 // M_aug @ Wqkv_i  (fp32)
__device__ float  g_Tdk [2 * 4 * 512];                // Mcx @ Wk_ca_i
__device__ float  g_Tq0 [4 * 512];                    // Mtx @ Wq_ca_0

static const long QBUF  = (long)RR * QW;              // QKV buffer stride (halfs)
static const long SSEGf = (long)8 * 1024 * 1024;      // S segment per combo (floats)
static const long ENCR  = (long)RR * 1024;            // one g_enc region (halfs)

// ---------------------------------------------------------------------------
// helpers
// ---------------------------------------------------------------------------
__device__ __forceinline__ void mma_f16(float c[4], const uint32_t a[4], const uint32_t b[2]) {
    asm volatile(
        "mma.sync.aligned.m16n8k16.row.col.f32.f16.f16.f32 "
        "{%0,%1,%2,%3}, {%4,%5,%6,%7}, {%8,%9}, {%0,%1,%2,%3};"
        : "+f"(c[0]), "+f"(c[1]), "+f"(c[2]), "+f"(c[3])
        : "r"(a[0]), "r"(a[1]), "r"(a[2]), "r"(a[3]), "r"(b[0]), "r"(b[1]));
}

__device__ __forceinline__ void cp16(uint32_t* dst, const void* src) {
    uint32_t d = (uint32_t)__cvta_generic_to_shared(dst);
    asm volatile("cp.async.cg.shared.global [%0], [%1], 16;" :: "r"(d), "l"(src));
}
#define CP_COMMIT() asm volatile("cp.async.commit_group;" ::: "memory")
#define CP_WAIT1()  asm volatile("cp.async.wait_group 1;"  ::: "memory")
#define CP_WAIT0()  asm volatile("cp.async.wait_group 0;"  ::: "memory")

struct Offs { long a[4]; long b[4]; long c[4]; };

// ---------------------------------------------------------------------------
// fp16 GEMM:  C[m,n] = alpha * sum_k A[m,k] * B[n,k]  [+bias] [+C]
// A: [M,K] row-major fp16 (lda); B: [N,K] row-major fp16 (ldb).
// C: fp32 (outHalf=0) or fp16 (outHalf=1).
// Tile 128x128x32, 256 threads (8 warps, warp tile 64x32), cp.async 2-stage.
// ---------------------------------------------------------------------------
#define WPR 20   // words per smem row (16 data + 4 pad)

__global__ void __launch_bounds__(256)
gemm_h(const __half* __restrict__ A, const __half* __restrict__ B,
       void* __restrict__ Cv, const float* __restrict__ bias,
       int K, int lda, int ldb, int ldc,
       long sAb, long sAh, long sBb, long sBh, long sCb, long sCh,
       int nh, int nzc, Offs off, float alpha, int accumulate, int outHalf)
{
    __shared__ uint32_t sA[2][128 * WPR];
    __shared__ uint32_t sB[2][128 * WPR];

    int z   = blockIdx.z;
    int cmb = z / nzc;
    int inn = z - cmb * nzc;
    int bb  = inn / nh;
    int hh  = inn - bb * nh;
    A += off.a[cmb] + (long)bb * sAb + (long)hh * sAh;
    B += off.b[cmb] + (long)bb * sBb + (long)hh * sBh;
    long coff = off.c[cmb] + (long)bb * sCb + (long)hh * sCh;

    const int row0 = blockIdx.y * 128;
    const int col0 = blockIdx.x * 128;
    const int tid  = threadIdx.x;
    const int wid  = tid >> 5;
    const int lane = tid & 31;
    const int wM0 = (wid & 1) * 64;
    const int wN0 = (wid >> 1) * 32;
    const int gid = lane >> 2;
    const int tig = lane & 3;

    float acc[4][4][4] = {};

    const int lrow = tid >> 1;
    const int lsel = tid & 1;

    auto loadTile = [&](int t, int s) {
        const __half* ga = A + (long)(row0 + lrow) * lda + t * 32 + lsel * 16;
        const __half* gb = B + (long)(col0 + lrow) * ldb + t * 32 + lsel * 16;
        uint32_t* sa = &sA[s][lrow * WPR + lsel * 8];
        uint32_t* sb = &sB[s][lrow * WPR + lsel * 8];
        cp16(sa, ga); cp16(sa + 4, ga + 8);
        cp16(sb, gb); cp16(sb + 4, gb + 8);
    };

    const int nT = K / 32;
    loadTile(0, 0);
    CP_COMMIT();

    for (int t = 0; t < nT; t++) {
        int s = t & 1;
        if (t + 1 < nT) {
            loadTile(t + 1, s ^ 1);
            CP_COMMIT();
            CP_WAIT1();
        } else {
            CP_WAIT0();
        }
        __syncthreads();

        const uint32_t* Ap = sA[s];
        const uint32_t* Bp = sB[s];
#pragma unroll
        for (int ko = 0; ko < 16; ko += 8) {
            uint32_t af[4][4], bfr[4][2];
#pragma unroll
            for (int mt = 0; mt < 4; mt++) {
                int m = wM0 + mt * 16 + gid;
                af[mt][0] = Ap[m * WPR + ko + tig];
                af[mt][1] = Ap[(m + 8) * WPR + ko + tig];
                af[mt][2] = Ap[m * WPR + ko + 4 + tig];
                af[mt][3] = Ap[(m + 8) * WPR + ko + 4 + tig];
            }
#pragma unroll
            for (int nt = 0; nt < 4; nt++) {
                int n = wN0 + nt * 8 + gid;
                bfr[nt][0] = Bp[n * WPR + ko + tig];
                bfr[nt][1] = Bp[n * WPR + ko + 4 + tig];
            }
#pragma unroll
            for (int mt = 0; mt < 4; mt++)
#pragma unroll
                for (int nt = 0; nt < 4; nt++)
                    mma_f16(acc[mt][nt], af[mt], bfr[nt]);
        }
        __syncthreads();
    }

    if (!outHalf) {
        float* C = (float*)Cv + coff;
#pragma unroll
        for (int mt = 0; mt < 4; mt++) {
            int r = row0 + wM0 + mt * 16 + gid;
#pragma unroll
            for (int nt = 0; nt < 4; nt++) {
                int c = col0 + wN0 + nt * 8 + tig * 2;
                float b0 = 0.f, b1 = 0.f;
                if (bias) { b0 = bias[c]; b1 = bias[c + 1]; }
                float2 v0, v1;
                v0.x = alpha * acc[mt][nt][0] + b0;
                v0.y = alpha * acc[mt][nt][1] + b1;
                v1.x = alpha * acc[mt][nt][2] + b0;
                v1.y = alpha * acc[mt][nt][3] + b1;
                float* p0 = &C[(long)r * ldc + c];
                float* p1 = &C[(long)(r + 8) * ldc + c];
                if (accumulate) {
                    float2 o0 = *(const float2*)p0, o1 = *(const float2*)p1;
                    v0.x += o0.x; v0.y += o0.y; v1.x += o1.x; v1.y += o1.y;
                }
                *(float2*)p0 = v0;
                *(float2*)p1 = v1;
            }
        }
    } else {
        __half* C = (__half*)Cv + coff;
#pragma unroll
        for (int mt = 0; mt < 4; mt++) {
            int r = row0 + wM0 + mt * 16 + gid;
#pragma unroll
            for (int nt = 0; nt < 4; nt++) {
                int c = col0 + wN0 + nt * 8 + tig * 2;
                __half2 h0 = __floats2half2_rn(alpha * acc[mt][nt][0], alpha * acc[mt][nt][1]);
                __half2 h1 = __floats2half2_rn(alpha * acc[mt][nt][2], alpha * acc[mt][nt][3]);
                *(__half2*)&C[(long)r * ldc + c]       = h0;
                *(__half2*)&C[(long)(r + 8) * ldc + c] = h1;
            }
        }
    }
}

// ---------------------------------------------------------------------------
// Single softmax (L=1024): S fp32 in, S16 fp16 out.
// ---------------------------------------------------------------------------
__global__ void softmax1(const float* __restrict__ S, __half* __restrict__ S16)
{
    const float4* p = (const float4*)(S + (long)blockIdx.x * 1024);
    __half2* o = (__half2*)(S16 + (long)blockIdx.x * 1024);
    int tid = threadIdx.x, lane = tid & 31, wid = tid >> 5;
    __shared__ float red[16];

    float4 v = p[tid];
    float m = fmaxf(fmaxf(v.x, v.y), fmaxf(v.z, v.w));
#pragma unroll
    for (int t = 16; t > 0; t >>= 1) m = fmaxf(m, __shfl_xor_sync(0xffffffffu, m, t));
    if (lane == 0) red[wid] = m;
    __syncthreads();
    m = red[0];
#pragma unroll
    for (int i = 1; i < 8; i++) m = fmaxf(m, red[i]);

    v.x = __expf(v.x - m); v.y = __expf(v.y - m);
    v.z = __expf(v.z - m); v.w = __expf(v.w - m);
    float sum = v.x + v.y + v.z + v.w;
#pragma unroll
    for (int t = 16; t > 0; t >>= 1) sum += __shfl_xor_sync(0xffffffffu, sum, t);
    if (lane == 0) red[8 + wid] = sum;
    __syncthreads();
    sum = red[8];
#pragma unroll
    for (int i = 1; i < 8; i++) sum += red[8 + i];
    float inv = 1.f / sum;

    o[2 * tid]     = __floats2half2_rn(v.x * inv, v.y * inv);
    o[2 * tid + 1] = __floats2half2_rn(v.z * inv, v.w * inv);
}

// ---------------------------------------------------------------------------
// Paired softmax + fold (cross layers): g=0 -> segs {0,2}, g=1 -> segs {1,3}.
// ---------------------------------------------------------------------------
__global__ void softmax_pair(const float* __restrict__ S, __half* __restrict__ S16)
{
    int bid = blockIdx.x;
    int g   = bid >> 13;
    int rem = bid & 8191;
    long roff = (long)rem << 10;
    const float4* pa = (const float4*)(S + (long)g * SSEGf + roff);
    const float4* pb = (const float4*)(S + (long)(g + 2) * SSEGf + roff);
    __half2* out = (__half2*)(S16 + ((long)rem << 11) + ((long)g << 10));
    int tid = threadIdx.x, lane = tid & 31, wid = tid >> 5;
    __shared__ float red[32];

    float4 va = pa[tid], vb = pb[tid];
    float ma = fmaxf(fmaxf(va.x, va.y), fmaxf(va.z, va.w));
    float mb = fmaxf(fmaxf(vb.x, vb.y), fmaxf(vb.z, vb.w));
#pragma unroll
    for (int t = 16; t > 0; t >>= 1) {
        ma = fmaxf(ma, __shfl_xor_sync(0xffffffffu, ma, t));
        mb = fmaxf(mb, __shfl_xor_sync(0xffffffffu, mb, t));
    }
    if (lane == 0) { red[wid] = ma; red[8 + wid] = mb; }
    __syncthreads();
    ma = red[0]; mb = red[8];
#pragma unroll
    for (int i = 1; i < 8; i++) { ma = fmaxf(ma, red[i]); mb = fmaxf(mb, red[8 + i]); }

    va.x = __expf(va.x - ma); va.y = __expf(va.y - ma);
    va.z = __expf(va.z - ma); va.w = __expf(va.w - ma);
    vb.x = __expf(vb.x - mb); vb.y = __expf(vb.y - mb);
    vb.z = __expf(vb.z - mb); vb.w = __expf(vb.w - mb);
    float sa = va.x + va.y + va.z + va.w;
    float sb = vb.x + vb.y + vb.z + vb.w;
#pragma unroll
    for (int t = 16; t > 0; t >>= 1) {
        sa += __shfl_xor_sync(0xffffffffu, sa, t);
        sb += __shfl_xor_sync(0xffffffffu, sb, t);
    }
    if (lane == 0) { red[16 + wid] = sa; red[24 + wid] = sb; }
    __syncthreads();
    sa = red[16]; sb = red[24];
#pragma unroll
    for (int i = 1; i < 8; i++) { sa += red[16 + i]; sb += red[24 + i]; }
    float ia = 1.f / sa, ib = 1.f / sb;

    out[2 * tid]     = __floats2half2_rn(va.x * ia + vb.x * ib, va.y * ia + vb.y * ib);
    out[2 * tid + 1] = __floats2half2_rn(va.z * ia + vb.z * ib, va.w * ia + vb.w * ib);
}

// ---------------------------------------------------------------------------
// transpose V head-slices: src [4*1024 rows, ldsrc] cols [512 + h*d, +d)
//  -> dst[z][d][dstLd] at column offset dstOff  (z = b*hn + h)
// ---------------------------------------------------------------------------
__global__ void transpose_v(const __half* __restrict__ src, __half* __restrict__ dst,
                            int ldsrc, int d, int hn, int dstLd, int dstOff)
{
    __shared__ __half t[32][34];
    int z = blockIdx.z;
    int b = z / hn, h = z - b * hn;
    int m0 = blockIdx.x * 32, c0 = blockIdx.y * 32;
    const __half* s = src + (long)(b * 1024) * ldsrc + 512 + h * d;
    int tx = threadIdx.x, ty = threadIdx.y;
#pragma unroll
    for (int i = 0; i < 4; i++)
        t[ty + i * 8][tx] = s[(long)(m0 + ty + i * 8) * ldsrc + c0 + tx];
    __syncthreads();
    __half* o = dst + (long)z * d * dstLd + dstOff;
#pragma unroll
    for (int i = 0; i < 4; i++)
        o[(long)(c0 + ty + i * 8) * dstLd + m0 + tx] = t[tx][ty + i * 8];
}

// ---------------------------------------------------------------------------
// out = LayerNorm(tmp + res) * g + b ; fp32 exact + fp16 state (ld 1024)
// ---------------------------------------------------------------------------
__global__ void add_ln_kernel(const float* __restrict__ tmp, const float* __restrict__ res,
                              const float* __restrict__ g, const float* __restrict__ b,
                              float* __restrict__ out, __half* __restrict__ outh)
{
    long row = blockIdx.x;
    const float* t = tmp + row * (long)HD;
    const float* r = res + row * (long)HD;
    float* o = out + row * (long)HD;
    __half* oh = outh + row * 1024;
    __shared__ float red[256];
    int tid = threadIdx.x;

    float v0 = t[tid]       + r[tid];
    float v1 = t[tid + 256] + r[tid + 256];
    red[tid] = v0 + v1; __syncthreads();
    for (int s = 128; s > 0; s >>= 1) { if (tid < s) red[tid] += red[tid + s]; __syncthreads(); }
    float mean = red[0] * (1.f / HD);
    __syncthreads();
    float d0 = v0 - mean, d1 = v1 - mean;
    red[tid] = d0 * d0 + d1 * d1; __syncthreads();
    for (int s = 128; s > 0; s >>= 1) { if (tid < s) red[tid] += red[tid + s]; __syncthreads(); }
    float rstd = rsqrtf(red[0] * (1.f / HD) + 1e-5f);
    float w0 = d0 * rstd * g[tid]       + b[tid];
    float w1 = d1 * rstd * g[tid + 256] + b[tid + 256];
    o[tid]       = w0;
    o[tid + 256] = w1;
    oh[tid]       = __float2half_rn(w0);
    oh[tid + 256] = __float2half_rn(w1);
}

// ---------------------------------------------------------------------------
// Input projections
// ---------------------------------------------------------------------------
__global__ void proj_in_kernel(const float* __restrict__ cx, const float* __restrict__ cy,
                               const float* __restrict__ W, const float* __restrict__ bias,
                               float* __restrict__ out, __half* __restrict__ outh,
                               int ldo, int j)
{
    int idx = blockIdx.x * blockDim.x + threadIdx.x;
    if (idx >= RR * HD) return;
    int r = idx >> 9;
    int h = idx & (HD - 1);
    float x0 = cx[r];
    float y0 = cy[r * 8 + j * 2];
    float y1 = cy[r * 8 + j * 2 + 1];
    float v = x0 * W[h] + y0 * W[HD + h] + y1 * W[2 * HD + h] + bias[h];
    if (out) out[idx] = v;
    outh[(long)r * ldo + h] = __float2half_rn(v);
}

__global__ void proj1_kernel(const float* __restrict__ x, const float* __restrict__ W,
                             const float* __restrict__ bias,
                             float* __restrict__ out, __half* __restrict__ outh, int ldo)
{
    int idx = blockIdx.x * blockDim.x + threadIdx.x;
    if (idx >= RR * HD) return;
    int r = idx >> 9;
    int h = idx & (HD - 1);
    float v = x[r] * W[h] + bias[h];
    if (out) out[idx] = v;
    outh[(long)r * ldo + h] = __float2half_rn(v);
}

// ---------------------------------------------------------------------------
// Rank-4 machinery
// ---------------------------------------------------------------------------
__global__ void build_F(const float* __restrict__ cx, const float* __restrict__ cy,
                        const float* __restrict__ tx,
                        float* __restrict__ F, float* __restrict__ Fdk,
                        float* __restrict__ Fdq)
{
    int r = blockIdx.x * blockDim.x + threadIdx.x;
    if (r >= RR) return;
    float c = cx[r];
#pragma unroll
    for (int s = 0; s < 4; s++) {
        float4 v = make_float4(c, cy[r * 8 + s * 2], cy[r * 8 + s * 2 + 1], 1.f);
        *(float4*)&F[((long)s * RR + r) * 4] = v;
    }
    *(float4*)&Fdk[r * 4] = make_float4(c, 1.f, 0.f, 0.f);
    *(float4*)&Fdq[r * 4] = make_float4(tx[r], 1.f, 0.f, 0.f);
}

// Tenc[i][k4][c(fused 1536)] = sum_k M_aug[k4][k] * W_{i,sel(c)}[k][c%512]
__global__ void tproj_enc(const float* __restrict__ Wk, const float* __restrict__ Wv,
                          const float* __restrict__ Wq, const float* __restrict__ inW,
                          const float* __restrict__ inb, float* __restrict__ T)
{
    int idx = blockIdx.x * blockDim.x + threadIdx.x;
    if (idx >= 2 * 4 * QW) return;
    int i   = idx / (4 * QW);
    int rem = idx - i * 4 * QW;
    int k4  = rem / QW;
    int c   = rem - k4 * QW;
    const float* W = (c < 512 ? Wk : c < 1024 ? Wv : Wq) + (long)i * 512 * 512;
    int n = c & 511;
    const float* m = (k4 < 3) ? (inW + k4 * 512) : inb;
    float s = 0.f;
    for (int k = 0; k < 512; k++) s += m[k] * W[(long)k * 512 + n];
    T[idx] = s;
}

// Tdk[i][k4][n] (k4<2 real, else 0); Tq0[k4][n] from layer-0 Wq.
__global__ void tproj_dec(const float* __restrict__ caWk, const float* __restrict__ caWq,
                          const float* __restrict__ cxW, const float* __restrict__ cxb,
                          const float* __restrict__ txW, const float* __restrict__ txb,
                          float* __restrict__ Tdk, float* __restrict__ Tq0)
{
    int idx = blockIdx.x * blockDim.x + threadIdx.x;
    if (idx >= 3 * 4 * 512) return;
    int grp = idx / (4 * 512);
    int rem = idx - grp * 4 * 512;
    int k4 = rem >> 9, n = rem & 511;
    float s = 0.f;
    if (grp < 2) {
        const float* W = caWk + (long)grp * 512 * 512;
        if (k4 == 0)      for (int k = 0; k < 512; k++) s += cxW[k] * W[(long)k * 512 + n];
        else if (k4 == 1) for (int k = 0; k < 512; k++) s += cxb[k] * W[(long)k * 512 + n];
        Tdk[grp * 2048 + rem] = s;
    } else {
        if (k4 == 0)      for (int k = 0; k < 512; k++) s += txW[k] * caWq[(long)k * 512 + n];
        else if (k4 == 1) for (int k = 0; k < 512; k++) s += txb[k] * caWq[(long)k * 512 + n];
        Tq0[rem] = s;
    }
}

// out[r][c] (ld QW) = fp16( F[r][:] . T[:][c] ), c in [0,1536)
__global__ void skinny_full(const float* __restrict__ F, const float* __restrict__ T,
                            __half* __restrict__ out)
{
    int idx = blockIdx.x * blockDim.x + threadIdx.x;
    if (idx >= RR * QW) return;
    int r = idx / QW, c = idx - r * QW;
    float4 f = *(const float4*)&F[(long)r * 4];
    float v = f.x * T[c] + f.y * T[QW + c] + f.z * T[2 * QW + c] + f.w * T[3 * QW + c];
    out[(long)r * QW + c] = __float2half_rn(v);
}

// out[r][outOff + c] (ld QW) over c in [0,512); T rows have leading dim tld.
__global__ void skinny_cols(const float* __restrict__ F, const float* __restrict__ T,
                            int tld, __half* __restrict__ out, int outOff)
{
    int idx = blockIdx.x * blockDim.x + threadIdx.x;
    if (idx >= RR * 512) return;
    int r = idx >> 9, c = idx & 511;
    float4 f = *(const float4*)&F[(long)r * 4];
    float v = f.x * T[c] + f.y * T[tld + c] + f.z * T[2 * tld + c] + f.w * T[3 * tld + c];
    out[(long)r * QW + outOff + c] = __float2half_rn(v);
}

// Direct transposed V for x2 streams (encoder, d=256, hn=2):
// Vt[z][dd][ld=2048] at off 1024; T = Tenc_i + 512 (V block, ld QW).
__global__ void skinny_vt(const float* __restrict__ F, const float* __restrict__ T,
                          __half* __restrict__ Vt)
{
    int idx = blockIdx.x * blockDim.x + threadIdx.x;
    if (idx >= 8 * 256 * 1024) return;
    int n = idx & 1023;
    int rest = idx >> 10;
    int dd = rest & 255;
    int z = rest >> 8;
    int b = z >> 1, h = z & 1;
    long r = (long)b * 1024 + n;
    int c = h * 256 + dd;
    float4 f = *(const float4*)&F[r * 4];
    float v = f.x * T[c] + f.y * T[QW + c] + f.z * T[2 * QW + c] + f.w * T[3 * QW + c];
    Vt[(long)z * 256 * 2048 + (long)dd * 2048 + 1024 + n] = __float2half_rn(v);
}

// ---------------------------------------------------------------------------
// Weight prep (tiled transposes)
// ---------------------------------------------------------------------------
__global__ void wprep_qkv(const float* __restrict__ sWk, const float* __restrict__ sWv,
                          const float* __restrict__ sWq, const float* __restrict__ cWk,
                          const float* __restrict__ cWv, const float* __restrict__ cWq,
                          __half* __restrict__ Wc)
{
    __shared__ float t[32][33];
    int z = blockIdx.z;
    int L = z / 3, m = z - L * 3;
    const float* base;
    if (L < 2) base = (m == 0 ? sWk : m == 1 ? sWv : sWq) + (long)L * 512 * 512;
    else       base = (m == 0 ? cWk : m == 1 ? cWv : cWq) + (long)(L - 2) * 512 * 512;
    __half* dst = Wc + (long)L * QW * 512 + (long)m * 512 * 512;
    int n0 = blockIdx.x * 32, k0 = blockIdx.y * 32;
    int tx = threadIdx.x, ty = threadIdx.y;
#pragma unroll
    for (int i = 0; i < 4; i++)
        t[ty + i * 8][tx] = base[(long)(k0 + ty + i * 8) * 512 + n0 + tx];
    __syncthreads();
#pragma unroll
    for (int i = 0; i < 4; i++)
        dst[(long)(n0 + ty + i * 8) * 512 + k0 + tx] = __float2half_rn(t[tx][ty + i * 8]);
}

__global__ void wprep_wf(const float* __restrict__ sWf, const float* __restrict__ cWf,
                         __half* __restrict__ Wf)
{
    __shared__ float t[32][33];
    int z = blockIdx.z;
    const float* src = (z < 2 ? sWf : cWf) + (long)(z & 1) * 1024 * 512;
    __half* dst = Wf + (long)z * 512 * 1024;
    int k0 = blockIdx.x * 32, n0 = blockIdx.y * 32;
    int tx = threadIdx.x, ty = threadIdx.y;
#pragma unroll
    for (int i = 0; i < 4; i++)
        t[ty + i * 8][tx] = src[(long)(k0 + ty + i * 8) * 512 + n0 + tx];
    __syncthreads();
#pragma unroll
    for (int i = 0; i < 4; i++)
        dst[(long)(n0 + ty + i * 8) * 1024 + k0 + tx] = __float2half_rn(t[tx][ty + i * 8]);
}

// ---------------------------------------------------------------------------
// Host orchestration
// ---------------------------------------------------------------------------
static void gemmH(const __half* A, const __half* B, void* C, const float* bias,
                  int M, int N, int K, int lda, int ldb, int ldc,
                  long sAb, long sAh, long sBb, long sBh, long sCb, long sCh,
                  int nb, int nh, int ncomb, const Offs& off,
                  float alpha, int acc, int outHalf)
{
    dim3 grid(N / 128, M / 128, ncomb * nb * nh);
    gemm_h<<<grid, 256>>>(A, B, C, bias, K, lda, ldb, ldc,
                          sAb, sAh, sBb, sBh, sCb, sCh,
                          nh, nb * nh, off, alpha, acc, outHalf);
}

struct Bufs {
    float *e, *qb, *T, *S, *F, *Fdk, *Fdq, *Tenc, *Tdk, *Tq0;
    __half *enc, *QKV, *Vt, *S16, *Wc, *Wf;
};

// Encoder layer. mode: 0 = self via skinny QKV (layer 1 only),
//                      1 = self via full GEMM, 2 = cross-domain.
static void sc_attn(Bufs& Z, int mode, const float* Fs, const float* Tl,
                    const __half* Wct, const __half* WfT,
                    const float* bf, const float* gg, const float* bb)
{
    const float scale = rsqrtf(256.f);
    Offs z0 = {};
    bool same = (mode != 2);
    const int nbF = (RR * QW + 255) / 256;
    const int nbC = (RR * 512 + 255) / 256;
    const int nbV = (8 * 256 * 1024 + 255) / 256;

    // state QKV
    if (mode == 0)
        skinny_full<<<nbF, 256>>>(Fs, Tl, Z.QKV);
    else
        gemmH(Z.enc, Wct, Z.QKV, nullptr, RR, QW, HD, 1024, HD, QW,
              0,0,0,0,0,0, 1,1,1, z0, 1.f, 0, 1);

    if (mode == 2) {
        // x2 stream via rank-4: K, Q into QKV2; V directly transposed into Vt
        skinny_cols<<<nbC, 256>>>(Fs, Tl,        QW, Z.QKV + QBUF, 0);
        skinny_cols<<<nbC, 256>>>(Fs, Tl + 1024, QW, Z.QKV + QBUF, 1024);
        skinny_vt<<<nbV, 256>>>(Fs, Tl + 512, Z.Vt);
        transpose_v<<<dim3(32, 8, 8), dim3(32, 8)>>>(Z.QKV, Z.Vt, QW, 256, 2, 2048, 0);
    } else {
        transpose_v<<<dim3(32, 8, 8), dim3(32, 8)>>>(Z.QKV, Z.Vt, QW, 256, 2, 1024, 0);
    }

    // QK scores -> S (fp32)
    {
        Offs oQK = {};
        int nc = 1;
        if (same) {
            oQK.a[0] = 1024;
        } else {
            const long selQ[4] = {0, 1, 1, 0};
            const long selK[4] = {0, 1, 0, 1};
            for (int c = 0; c < 4; c++) {
                oQK.a[c] = selQ[c] * QBUF + 1024;
                oQK.b[c] = selK[c] * QBUF;
                oQK.c[c] = c * SSEGf;
            }
            nc = 4;
        }
        gemmH(Z.QKV, Z.QKV, Z.S, nullptr, 1024, 1024, 256, QW, QW, 1024,
              (long)1024 * QW, 256, (long)1024 * QW, 256,
              (long)2 * 1024 * 1024, (long)1024 * 1024,
              4, 2, nc, oQK, scale, 0, 0);
    }

    if (same) {
        softmax1<<<8 * 1024, 256>>>(Z.S, Z.S16);
        gemmH(Z.S16, Z.Vt, Z.enc + 512, nullptr, 1024, 256, 1024, 1024, 1024, 1024,
              (long)2 * 1024 * 1024, (long)1024 * 1024,
              (long)2 * 256 * 1024, (long)256 * 1024,
              (long)1024 * 1024, 256,
              4, 2, 1, z0, 4.f, 0, 1);
    } else {
        softmax_pair<<<2 * 8 * 1024, 256>>>(Z.S, Z.S16);
        gemmH(Z.S16, Z.Vt, Z.enc + 512, nullptr, 1024, 256, 2048, 2048, 2048, 1024,
              (long)2 * 1024 * 2048, (long)1024 * 2048,
              (long)2 * 256 * 2048, (long)256 * 2048,
              (long)1024 * 1024, 256,
              4, 2, 1, z0, 1.f, 0, 1);
    }

    gemmH(Z.enc, WfT, Z.T, bf, RR, HD, 1024, 1024, 1024, HD,
          0,0,0,0,0,0, 1,1,1, z0, 1.f, 0, 0);

    add_ln_kernel<<<RR, 256>>>(Z.T, Z.e, gg, bb, Z.e, Z.enc);
}

// Decoder cross-attn layer (h=4, d=128). State: g_qb + xrq (= enc region 2).
static void cross_attn(Bufs& Z, int i, const __half* Wct, const __half* WfT,
                       const float* bf, const float* gg, const float* bb)
{
    const float scale = rsqrtf(128.f);
    Offs z0 = {};
    __half* xrq = Z.enc + 2 * ENCR;
    const int nbC = (RR * 512 + 255) / 256;

    if (i == 0) {
        // V proj (full) + skinny Q from rank-2 target projection
        Offs oV = {}; oV.b[0] = (long)512 * 512; oV.c[0] = 512;
        gemmH(Z.enc, Wct, Z.QKV, nullptr, RR, 512, HD, 1024, HD, QW,
              0,0,0,0,0,0, 1,1,1, oV, 1.f, 0, 1);
        skinny_cols<<<nbC, 256>>>(Z.Fdq, Z.Tq0, 512, Z.QKV, 1024);
    } else {
        // batched {V from encoder state, Q from decoder state}
        Offs oVQ = {};
        oVQ.a[0] = 0;        oVQ.b[0] = (long)512 * 512;  oVQ.c[0] = 512;
        oVQ.a[1] = 2 * ENCR; oVQ.b[1] = (long)1024 * 512; oVQ.c[1] = 1024;
        gemmH(Z.enc, Wct, Z.QKV, nullptr, RR, 512, HD, 1024, HD, QW,
              0,0,0,0,0,0, 1,1,2, oVQ, 1.f, 0, 1);
    }
    // K from rank-2 context projection
    skinny_cols<<<nbC, 256>>>(Z.Fdk, Z.Tdk + (long)i * 4 * 512, 512, Z.QKV, 0);

    transpose_v<<<dim3(32, 4, 16), dim3(32, 8)>>>(Z.QKV, Z.Vt, QW, 128, 4, 1024, 0);

    Offs oQK = {}; oQK.a[0] = 1024;
    gemmH(Z.QKV, Z.QKV, Z.S, nullptr, 1024, 1024, 128, QW, QW, 1024,
          (long)1024 * QW, 128, (long)1024 * QW, 128,
          (long)4 * 1024 * 1024, (long)1024 * 1024,
          4, 4, 1, oQK, scale, 0, 0);

    softmax1<<<16 * 1024, 256>>>(Z.S, Z.S16);

    gemmH(Z.S16, Z.Vt, xrq + 512, nullptr, 1024, 128, 1024, 1024, 1024, 1024,
          (long)4 * 1024 * 1024, (long)1024 * 1024,
          (long)4 * 128 * 1024, (long)128 * 1024,
          (long)1024 * 1024, 128,
          4, 4, 1, z0, 1.f, 0, 1);

    gemmH(xrq, WfT, Z.T, bf, RR, HD, 1024, 1024, 1024, HD,
          0,0,0,0,0,0, 1,1,1, z0, 1.f, 0, 0);

    add_ln_kernel<<<RR, 256>>>(Z.T, Z.qb, gg, bb, Z.qb, xrq);
}

extern "C" void kernel_launch(void* const* d_in, const int* in_sizes, int n_in,
                              void* d_out, int out_size)
{
    const float* context_x = (const float*)d_in[0];
    const float* context_y = (const float*)d_in[1];
    const float* target_x  = (const float*)d_in[2];
    const float* in_W = (const float*)d_in[3];
    const float* in_b = (const float*)d_in[4];
    const float* cx_W = (const float*)d_in[5];
    const float* cx_b = (const float*)d_in[6];
    const float* tx_W = (const float*)d_in[7];
    const float* tx_b = (const float*)d_in[8];
    const float* sc_Wk = (const float*)d_in[9];
    const float* sc_Wv = (const float*)d_in[10];
    const float* sc_Wq = (const float*)d_in[11];
    const float* sc_Wf = (const float*)d_in[12];
    const float* sc_bf = (const float*)d_in[13];
    const float* sc_g  = (const float*)d_in[14];
    const float* sc_b  = (const float*)d_in[15];
    const float* ca_Wk = (const float*)d_in[16];
    const float* ca_Wv = (const float*)d_in[17];
    const float* ca_Wq = (const float*)d_in[18];
    const float* ca_Wf = (const float*)d_in[19];
    const float* ca_bf = (const float*)d_in[20];
    const float* ca_g  = (const float*)d_in[21];
    const float* ca_b  = (const float*)d_in[22];

    Bufs Z;
    cudaGetSymbolAddress((void**)&Z.e,    g_e);
    cudaGetSymbolAddress((void**)&Z.qb,   g_qb);
    cudaGetSymbolAddress((void**)&Z.T,    g_T);
    cudaGetSymbolAddress((void**)&Z.S,    g_S);
    cudaGetSymbolAddress((void**)&Z.enc,  g_enc);
    cudaGetSymbolAddress((void**)&Z.QKV,  g_QKV);
    cudaGetSymbolAddress((void**)&Z.Vt,   g_Vt);
    cudaGetSymbolAddress((void**)&Z.S16,  g_S16);
    cudaGetSymbolAddress((void**)&Z.Wc,   g_Wc);
    cudaGetSymbolAddress((void**)&Z.Wf,   g_Wf);
    cudaGetSymbolAddress((void**)&Z.F,    g_F);
    cudaGetSymbolAddress((void**)&Z.Fdk,  g_Fdk);
    cudaGetSymbolAddress((void**)&Z.Fdq,  g_Fdq);
    cudaGetSymbolAddress((void**)&Z.Tenc, g_Tenc);
    cudaGetSymbolAddress((void**)&Z.Tdk,  g_Tdk);
    cudaGetSymbolAddress((void**)&Z.Tq0,  g_Tq0);

    const long WCL = (long)QW * 512;     // fused QKV weight per layer (halfs)
    const long WFL = (long)512 * 1024;   // Wf per layer (halfs)

    // ---- prep ----
    wprep_qkv<<<dim3(16, 16, 12), dim3(32, 8)>>>(sc_Wk, sc_Wv, sc_Wq,
                                                 ca_Wk, ca_Wv, ca_Wq, Z.Wc);
    wprep_wf<<<dim3(32, 16, 4), dim3(32, 8)>>>(sc_Wf, ca_Wf, Z.Wf);
    build_F<<<(RR + 255) / 256, 256>>>(context_x, context_y, target_x,
                                       Z.F, Z.Fdk, Z.Fdq);
    tproj_enc<<<(2 * 4 * QW + 255) / 256, 256>>>(sc_Wk, sc_Wv, sc_Wq, in_W, in_b, Z.Tenc);
    tproj_dec<<<(3 * 4 * 512 + 255) / 256, 256>>>(ca_Wk, ca_Wq, cx_W, cx_b,
                                                  tx_W, tx_b, Z.Tdk, Z.Tq0);

    const int nthr = 256, nblk = (RR * HD + nthr - 1) / nthr;

    // encoder state e (fp32 exact + fp16 region0)
    proj_in_kernel<<<nblk, nthr>>>(context_x, context_y, in_W, in_b, Z.e, Z.enc, 1024, 0);

    // ---- encoder: 2 self layers (layer 1 via skinny QKV), then 3x2 cross ----
    sc_attn(Z, 0, Z.F, Z.Tenc, Z.Wc, Z.Wf,
            sc_bf, sc_g, sc_b);
    sc_attn(Z, 1, nullptr, nullptr, Z.Wc + WCL, Z.Wf + WFL,
            sc_bf + HD, sc_g + HD, sc_b + HD);

    for (int s = 1; s <= 3; s++)
        for (int i = 0; i < 2; i++)
            sc_attn(Z, 2, Z.F + (long)s * RR * 4, Z.Tenc + (long)i * 4 * QW,
                    Z.Wc + i * WCL, Z.Wf + i * WFL,
                    sc_bf + i * HD, sc_g + i * HD, sc_b + i * HD);

    // ---- decoder ----
    proj1_kernel<<<nblk, nthr>>>(target_x, tx_W, tx_b, Z.qb, Z.enc + 2 * ENCR, 1024);

    for (int i = 0; i < 2; i++)
        cross_attn(Z, i, Z.Wc + (2 + i) * WCL, Z.Wf + (2 + i) * WFL,
                   ca_bf + i * HD, ca_g + i * HD, ca_b + i * HD);

    cudaMemcpyAsync(d_out, Z.qb, (size_t)RR * HD * sizeof(float),
                    cudaMemcpyDeviceToDevice);
}